// round 13
// baseline (speedup 1.0000x reference)
#include <cuda_runtime.h>
#include <cuda_bf16.h>
#include <math.h>
#include <stdint.h>

#define QLEN  2048
#define BSZ   2
#define NH    16
#define DH    64
#define DM    1024
#define KLEN  2048
#define RLEN  2048
// 0.125 * log2(e): scores stored in base-2 domain so softmax uses 2^x
#define SCALE_L2E 0.1803368801111244f

// ---------------- scratch (device globals) ----------------------------------
__device__ float g_Qb[(size_t)BSZ * NH * QLEN * DH];   // Q + r_r_bias, (b,n,q,d)
__device__ float g_K [(size_t)BSZ * NH * KLEN * DH];   // (b,n,k,d)
__device__ float g_V [(size_t)BSZ * NH * KLEN * DH];   // (b,n,k,d)
__device__ float g_Rk[(size_t)NH * RLEN * DH];         // (n,r,d)
__device__ float g_AV[(size_t)QLEN * BSZ * DM];        // attn_vec (q,b,n*d)
__device__ float g_negmask[(size_t)BSZ * KLEN];        // 0 or -inf, [b][k]

// ---------------- helpers -----------------------------------------------------
__device__ __forceinline__ uint32_t f2tf(float f) {
    uint32_t u; asm("cvt.rna.tf32.f32 %0, %1;" : "=r"(u) : "f"(f)); return u;
}
__device__ __forceinline__ void mma8(float* c, const uint32_t* a, const uint32_t* b) {
    asm volatile(
        "mma.sync.aligned.m16n8k8.row.col.f32.tf32.tf32.f32 "
        "{%0,%1,%2,%3}, {%4,%5,%6,%7}, {%8,%9}, {%0,%1,%2,%3};"
        : "+f"(c[0]), "+f"(c[1]), "+f"(c[2]), "+f"(c[3])
        : "r"(a[0]), "r"(a[1]), "r"(a[2]), "r"(a[3]), "r"(b[0]), "r"(b[1]));
}
// branch-free 2^t on FMA/ALU pipes. t <= 0 expected; -inf -> ~0.
__device__ __forceinline__ float fexp2(float t) {
    t = fmaxf(t, -126.0f);
    float u = t + 12582912.0f;
    int ki = __float_as_int(u) - 0x4B400000;
    float fk = u - 12582912.0f;
    float f = t - fk;
    float p = 0.0013333558f;
    p = fmaf(p, f, 0.0096181291f);
    p = fmaf(p, f, 0.0555041087f);
    p = fmaf(p, f, 0.2402265069f);
    p = fmaf(p, f, 0.6931471806f);
    p = fmaf(p, f, 1.0f);
    return __int_as_float(__float_as_int(p) + (ki << 23));
}

// ---------------- mask detect + expand (validated) ---------------------------
__global__ void mask_expand_kernel(const unsigned char* __restrict__ m) {
    __shared__ int cnt[4];
    __shared__ int smode;
    if (threadIdx.x < 4) cnt[threadIdx.x] = 0;
    __syncthreads();
    for (int i = threadIdx.x; i < 4096; i += blockDim.x)
        if (m[i]) atomicAdd(&cnt[i & 3], 1);
    __syncthreads();
    if (threadIdx.x == 0) {
        int mode;
        if (cnt[1] == 0 && cnt[2] == 0 && cnt[3] == 0) mode = 0;      // int32
        else if (cnt[0] == 0 && cnt[1] == 0)           mode = 1;      // float32
        else                                           mode = 2;      // bool byte
        smode = mode;
    }
    __syncthreads();
    int mode = smode;
    for (int idx = threadIdx.x; idx < KLEN * BSZ; idx += blockDim.x) {
        bool msk;
        if (mode == 0)      msk = ((const int*)m)[idx] != 0;
        else if (mode == 1) msk = ((const float*)m)[idx] != 0.0f;
        else                msk = m[idx] != 0;
        int k = idx >> 1, b = idx & 1;
        g_negmask[b * KLEN + k] = msk ? -INFINITY : 0.0f;
    }
}

// =============================================================================
// NN TF32 MMA GEMM body (validated round 6)
// =============================================================================
#define NN_TF32_BODY(Aptr, Bptr, Kdim, Ndim, ...)                               \
    __shared__ uint32_t As[128][36];                                            \
    __shared__ uint32_t Bs[32][136];                                            \
    int tid = threadIdx.x;                                                      \
    int row0 = blockIdx.y * 128, col0 = blockIdx.x * 128;                       \
    int wid = tid >> 5, lane = tid & 31, g = lane >> 2, t = lane & 3;           \
    int wm = (wid & 3) * 32, wn = (wid >> 2) * 64;                              \
    (void)lane;                                                                 \
    float c[2][8][4] = {};                                                      \
    float4 pa[4], pb[4];                                                        \
    _Pragma("unroll")                                                           \
    for (int i = 0; i < 4; i++) {                                               \
        int f4 = tid + i * 256;                                                 \
        int rw = f4 >> 3, c4 = (f4 & 7) * 4;                                    \
        pa[i] = *(const float4*)&Aptr[(size_t)(row0 + rw) * Kdim + c4];         \
        int brw = f4 >> 5, bc4 = (f4 & 31) * 4;                                 \
        pb[i] = *(const float4*)&Bptr[(size_t)brw * Ndim + col0 + bc4];         \
    }                                                                           \
    for (int k0c = 0; k0c < Kdim; k0c += 32) {                                  \
        _Pragma("unroll")                                                       \
        for (int i = 0; i < 4; i++) {                                           \
            int f4 = tid + i * 256;                                             \
            int rw = f4 >> 3, c4 = (f4 & 7) * 4;                                \
            *(uint4*)&As[rw][c4] =                                              \
                make_uint4(f2tf(pa[i].x), f2tf(pa[i].y), f2tf(pa[i].z), f2tf(pa[i].w)); \
            int brw = f4 >> 5, bc4 = (f4 & 31) * 4;                             \
            *(uint4*)&Bs[brw][bc4] =                                            \
                make_uint4(f2tf(pb[i].x), f2tf(pb[i].y), f2tf(pb[i].z), f2tf(pb[i].w)); \
        }                                                                       \
        __syncthreads();                                                        \
        if (k0c + 32 < Kdim) {                                                  \
            _Pragma("unroll")                                                   \
            for (int i = 0; i < 4; i++) {                                       \
                int f4 = tid + i * 256;                                         \
                int rw = f4 >> 3, c4 = (f4 & 7) * 4;                            \
                pa[i] = *(const float4*)&Aptr[(size_t)(row0 + rw) * Kdim + k0c + 32 + c4]; \
                int brw = f4 >> 5, bc4 = (f4 & 31) * 4;                         \
                pb[i] = *(const float4*)&Bptr[(size_t)(k0c + 32 + brw) * Ndim + col0 + bc4]; \
            }                                                                   \
        }                                                                       \
        _Pragma("unroll")                                                       \
        for (int k0 = 0; k0 < 32; k0 += 8) {                                    \
            uint32_t a[2][4], b2[8][2];                                         \
            _Pragma("unroll")                                                   \
            for (int mt = 0; mt < 2; mt++) {                                    \
                int r = wm + mt * 16 + g;                                       \
                a[mt][0] = As[r][k0 + t];     a[mt][1] = As[r + 8][k0 + t];     \
                a[mt][2] = As[r][k0 + t + 4]; a[mt][3] = As[r + 8][k0 + t + 4]; \
            }                                                                   \
            _Pragma("unroll")                                                   \
            for (int nt = 0; nt < 8; nt++) {                                    \
                int cn = wn + nt * 8 + g;                                       \
                b2[nt][0] = Bs[k0 + t][cn];                                     \
                b2[nt][1] = Bs[k0 + t + 4][cn];                                 \
            }                                                                   \
            _Pragma("unroll")                                                   \
            for (int mt = 0; mt < 2; mt++)                                      \
                _Pragma("unroll")                                               \
                for (int nt = 0; nt < 8; nt++) mma8(c[mt][nt], a[mt], b2[nt]);  \
        }                                                                       \
        __syncthreads();                                                        \
    }                                                                           \
    __VA_ARGS__

// ---------------- GEMM 1: heads = w @ qkv_w -> Qb/K/V (TF32) -----------------
__global__ __launch_bounds__(256)
void gemm_qkv_kernel(const float* __restrict__ A, const float* __restrict__ B,
                     const float* __restrict__ rbias) {
    NN_TF32_BODY(A, B, 1024, 3072, {
        for (int mt = 0; mt < 2; mt++) {
            for (int rr = 0; rr < 2; rr++) {
                int m = row0 + wm + mt * 16 + g + rr * 8;
                int q = m >> 1;
                int bb = m & 1;
                for (int nt = 0; nt < 8; nt++) {
                    int cc = col0 + wn + nt * 8 + 2 * t;
                    int sec = cc >> 10;
                    int h = (cc & 1023) >> 6;
                    int d = cc & 63;
                    size_t off = ((size_t)(bb * NH + h) * QLEN + q) * DH + d;
                    float vx = c[mt][nt][rr * 2 + 0];
                    float vy = c[mt][nt][rr * 2 + 1];
                    if (sec == 0) {
                        float2 rb = *(const float2*)&rbias[h * 64 + d];
                        float2 v;
                        v.x = vx + rb.x;
                        v.y = vy + rb.y;
                        *(float2*)&g_Qb[off] = v;
                    } else if (sec == 1) {
                        float2 v; v.x = vx; v.y = vy;
                        *(float2*)&g_K[off] = v;
                    } else {
                        float2 v; v.x = vx; v.y = vy;
                        *(float2*)&g_V[off] = v;
                    }
                }
            }
        }
    })
}

// ---------------- GEMM 2: r_head_k = r @ r_net_w -> Rk (TF32) ----------------
__global__ __launch_bounds__(256)
void gemm_rnet_kernel(const float* __restrict__ A, const float* __restrict__ B) {
    NN_TF32_BODY(A, B, 1024, 1024, {
        for (int mt = 0; mt < 2; mt++) {
            for (int rr = 0; rr < 2; rr++) {
                int m = row0 + wm + mt * 16 + g + rr * 8;
                for (int nt = 0; nt < 8; nt++) {
                    int cc = col0 + wn + nt * 8 + 2 * t;
                    int h = cc >> 6;
                    int d = cc & 63;
                    float2 v;
                    v.x = c[mt][nt][rr * 2 + 0];
                    v.y = c[mt][nt][rr * 2 + 1];
                    *(float2*)&g_Rk[((size_t)h * RLEN + m) * DH + d] = v;
                }
            }
        }
    })
}

// ---------------- GEMM 6: output = attn_vec @ o_w (TF32) ---------------------
__global__ __launch_bounds__(256)
void gemm_out_kernel(const float* __restrict__ B, float* __restrict__ out) {
    const float* A = g_AV;
    NN_TF32_BODY(A, B, 1024, 1024, {
        for (int mt = 0; mt < 2; mt++) {
            for (int rr = 0; rr < 2; rr++) {
                int m = row0 + wm + mt * 16 + g + rr * 8;
                for (int nt = 0; nt < 8; nt++) {
                    int cc = col0 + wn + nt * 8 + 2 * t;
                    float2 v;
                    v.x = c[mt][nt][rr * 2 + 0];
                    v.y = c[mt][nt][rr * 2 + 1];
                    *(float2*)&out[(size_t)m * 1024 + cc] = v;
                }
            }
        }
    })
}

// =============================================================================
// Fused score kernel: 512 threads, 129-row Q buffer (band qoff via +1 row
// index, no Q reloads), 4 column tiles per CTA (Q amortized).
// SMEM: BDs[128][260] | Qs[129][68] | Ks[128][68]
// =============================================================================
#define SMEM_STRIDE 68
#define BD_STRIDE 260
#define BD_WORDS (128 * BD_STRIDE)

__global__ __launch_bounds__(512, 1)
void score_fused_kernel(float* __restrict__ cov) {
    extern __shared__ uint32_t sm[];
    float* BDs = (float*)sm;                                   // 128 x 260 floats
    uint32_t (*Qs)[SMEM_STRIDE] = (uint32_t(*)[SMEM_STRIDE])(sm + BD_WORDS);            // 129 rows
    uint32_t (*Ks)[SMEM_STRIDE] = (uint32_t(*)[SMEM_STRIDE])(sm + BD_WORDS + 129 * SMEM_STRIDE);

    int z = blockIdx.z;
    int b = z >> 4;
    int n = z & (NH - 1);
    const float* Qp  = g_Qb + (size_t)z * QLEN * DH;
    const float* Kp  = g_K  + (size_t)z * KLEN * DH;
    const float* Rkn = g_Rk + (size_t)n * RLEN * DH;
    int row0 = blockIdx.y * 128;
    int tid = threadIdx.x;
    int wid = tid >> 5, lane = tid & 31, g = lane >> 2, t = lane & 3;
    int wm = (wid & 3) * 32, wn = (wid >> 2) * 32;   // 4x4 warp grid, 32x32 tiles

    // ---- load Q once: rows row0..row0+128 (129 rows; last clamped) ----
#pragma unroll
    for (int i = 0; i < 4; i++) {
        int f4 = tid + i * 512;
        int rw = f4 >> 4, c4 = (f4 & 15) * 4;
        float4 qa = *(const float4*)&Qp[(size_t)(row0 + rw) * DH + c4];
        *(uint4*)&Qs[rw][c4] = make_uint4(f2tf(qa.x), f2tf(qa.y), f2tf(qa.z), f2tf(qa.w));
    }
    if (tid < 16) {
        int qr = row0 + 128; if (qr > 2047) qr = 2047;
        int c4 = tid * 4;
        float4 qa = *(const float4*)&Qp[(size_t)qr * DH + c4];
        *(uint4*)&Qs[128][c4] = make_uint4(f2tf(qa.x), f2tf(qa.y), f2tf(qa.z), f2tf(qa.w));
    }
    // (covered by the sync after the first K-tile load)

    const float* neg = g_negmask + (size_t)b * KLEN;
    float* Cz = cov + (size_t)z * QLEN * KLEN;

#pragma unroll 1
    for (int ct = 0; ct < 4; ct++) {
        int col0 = (blockIdx.x * 4 + ct) * 128;

        // ---- K tile load ----
#pragma unroll
        for (int i = 0; i < 4; i++) {
            int f4 = tid + i * 512;
            int rw = f4 >> 4, c4 = (f4 & 15) * 4;
            float4 kb = *(const float4*)&Kp[(size_t)(col0 + rw) * DH + c4];
            *(uint4*)&Ks[rw][c4] = make_uint4(f2tf(kb.x), f2tf(kb.y), f2tf(kb.z), f2tf(kb.w));
        }
        __syncthreads();

        // ---- AC MMA ----
        float c[2][4][4] = {};
#pragma unroll
        for (int k0 = 0; k0 < 64; k0 += 8) {
            uint32_t a[2][4], b2[4][2];
#pragma unroll
            for (int mt = 0; mt < 2; mt++) {
                int r = wm + mt * 16 + g;
                a[mt][0] = Qs[r][k0 + t];     a[mt][1] = Qs[r + 8][k0 + t];
                a[mt][2] = Qs[r][k0 + t + 4]; a[mt][3] = Qs[r + 8][k0 + t + 4];
            }
#pragma unroll
            for (int nt = 0; nt < 4; nt++) {
                int r = wn + nt * 8 + g;
                b2[nt][0] = Ks[r][k0 + t];
                b2[nt][1] = Ks[r][k0 + t + 4];
            }
#pragma unroll
            for (int mt = 0; mt < 2; mt++)
#pragma unroll
                for (int nt = 0; nt < 4; nt++) mma8(c[mt][nt], a[mt], b2[nt]);
        }
        __syncthreads();

        // ---- band parameters (validated round 10) ----
        int below = (col0 < row0);
        int diag  = (col0 == row0);
        int d0 = col0 - row0;
        int qoffA   = (below || diag) ? 0 : 1;
        int rstartA = (below || diag) ? (1920 + d0) : (d0 - 129);
        int qoffB   = below ? 0 : 1;
        int rstartB = below ? (1920 + d0 + 128) : (diag ? -1 : (d0 - 129 + 128));

#pragma unroll 1
        for (int half = 0; half < 2; half++) {
            int qoff   = half ? qoffB : qoffA;
            int rstart = half ? rstartB : rstartA;
#pragma unroll
            for (int i = 0; i < 4; i++) {
                int f4 = tid + i * 512;
                int rw = f4 >> 4, c4 = (f4 & 15) * 4;
                int rr_ = rstart + rw; if (rr_ < 0) rr_ = 0; if (rr_ > 2047) rr_ = 2047;
                float4 kb = *(const float4*)&Rkn[(size_t)rr_ * DH + c4];
                *(uint4*)&Ks[rw][c4] = make_uint4(f2tf(kb.x), f2tf(kb.y), f2tf(kb.z), f2tf(kb.w));
            }
            __syncthreads();
            float c2[2][4][4] = {};
#pragma unroll
            for (int k0 = 0; k0 < 64; k0 += 8) {
                uint32_t a[2][4], b2[4][2];
#pragma unroll
                for (int mt = 0; mt < 2; mt++) {
                    int r = wm + mt * 16 + g + qoff;   // 129-row Q: qoff via row index
                    a[mt][0] = Qs[r][k0 + t];     a[mt][1] = Qs[r + 8][k0 + t];
                    a[mt][2] = Qs[r][k0 + t + 4]; a[mt][3] = Qs[r + 8][k0 + t + 4];
                }
#pragma unroll
                for (int nt = 0; nt < 4; nt++) {
                    int r = wn + nt * 8 + g;
                    b2[nt][0] = Ks[r][k0 + t];
                    b2[nt][1] = Ks[r][k0 + t + 4];
                }
#pragma unroll
                for (int mt = 0; mt < 2; mt++)
#pragma unroll
                    for (int nt = 0; nt < 4; nt++) mma8(c2[mt][nt], a[mt], b2[nt]);
            }
            // stage raw half into BDs columns [half*128, half*128+128)
#pragma unroll
            for (int mt = 0; mt < 2; mt++)
#pragma unroll
                for (int nt = 0; nt < 4; nt++)
#pragma unroll
                    for (int rr = 0; rr < 2; rr++) {
                        int r = wm + mt * 16 + g + rr * 8;
                        int ccol = half * 128 + wn + nt * 8 + 2 * t;
                        float2 v;
                        v.x = c2[mt][nt][rr * 2 + 0];
                        v.y = c2[mt][nt][rr * 2 + 1];
                        *(float2*)&BDs[r * BD_STRIDE + ccol] = v;
                    }
            __syncthreads();
        }

        // ---- epilogue: s = (AC + BDs[qi][127+ki-qi]) * scale + negmask ----
#pragma unroll
        for (int mt = 0; mt < 2; mt++) {
            int qi0 = wm + mt * 16 + g;
#pragma unroll
            for (int nt = 0; nt < 4; nt++) {
                int kloc = wn + nt * 8 + 2 * t;
                int kb = col0 + kloc;
                float2 ng = *(const float2*)&neg[kb];
#pragma unroll
                for (int rr = 0; rr < 2; rr++) {
                    int qi = qi0 + rr * 8;
                    int q = row0 + qi;
                    int jj = 127 + kloc - qi;
                    float bdx = (kb     == q + 1) ? 0.0f : BDs[qi * BD_STRIDE + jj];
                    float bdy = (kb + 1 == q + 1) ? 0.0f : BDs[qi * BD_STRIDE + jj + 1];
                    float2 s;
                    s.x = (c[mt][nt][rr * 2 + 0] + bdx) * SCALE_L2E + ng.x;
                    s.y = (c[mt][nt][rr * 2 + 1] + bdy) * SCALE_L2E + ng.y;
                    *(float2*)&Cz[(size_t)q * KLEN + kb] = s;
                }
            }
        }
        // next tile's K load (writes Ks only) is safe to overlap; BDs rewrite
        // is >= 3 barriers away.
    }
}

// ---------------- softmax over k (validated; base-2 domain) ------------------
__global__ __launch_bounds__(256)
void softmax_kernel(float* __restrict__ cov) {
    size_t row = blockIdx.x;
    float* p = cov + row * KLEN;
    int t = threadIdx.x;
    float4 v0 = ((const float4*)p)[t];
    float4 v1 = ((const float4*)p)[t + 256];
    float m = fmaxf(fmaxf(fmaxf(v0.x, v0.y), fmaxf(v0.z, v0.w)),
                    fmaxf(fmaxf(v1.x, v1.y), fmaxf(v1.z, v1.w)));
    __shared__ float sred[8];
#pragma unroll
    for (int o = 16; o; o >>= 1) m = fmaxf(m, __shfl_xor_sync(0xffffffffu, m, o));
    if ((t & 31) == 0) sred[t >> 5] = m;
    __syncthreads();
    if (t < 8) {
        float x = sred[t];
#pragma unroll
        for (int o = 4; o; o >>= 1) x = fmaxf(x, __shfl_xor_sync(0xffu, x, o));
        if (t == 0) sred[0] = x;
    }
    __syncthreads();
    m = sred[0];
    if (m == -INFINITY) {   // fully-masked row -> 0 per reference
        float4 zz = make_float4(0.f, 0.f, 0.f, 0.f);
        ((float4*)p)[t] = zz;
        ((float4*)p)[t + 256] = zz;
        return;
    }
    float e0x = fexp2(v0.x - m), e0y = fexp2(v0.y - m);
    float e0z = fexp2(v0.z - m), e0w = fexp2(v0.w - m);
    float e1x = fexp2(v1.x - m), e1y = fexp2(v1.y - m);
    float e1z = fexp2(v1.z - m), e1w = fexp2(v1.w - m);
    float s = (e0x + e0y) + (e0z + e0w) + (e1x + e1y) + (e1z + e1w);
    __shared__ float ssum[8];
#pragma unroll
    for (int o = 16; o; o >>= 1) s += __shfl_xor_sync(0xffffffffu, s, o);
    if ((t & 31) == 0) ssum[t >> 5] = s;
    __syncthreads();
    if (t < 8) {
        float x = ssum[t];
#pragma unroll
        for (int o = 4; o; o >>= 1) x += __shfl_xor_sync(0xffu, x, o);
        if (t == 0) ssum[0] = x;
    }
    __syncthreads();
    float inv = 1.0f / ssum[0];
    ((float4*)p)[t]       = make_float4(e0x * inv, e0y * inv, e0z * inv, e0w * inv);
    ((float4*)p)[t + 256] = make_float4(e1x * inv, e1y * inv, e1z * inv, e1w * inv);
}

// ---------------- PV: attn_vec = P @ V (TF32 MMA, validated r6) --------------
__global__ __launch_bounds__(256)
void pv_mma_kernel(const float* __restrict__ cov) {
    extern __shared__ uint32_t sm[];
    uint32_t (*Ps)[SMEM_STRIDE] = (uint32_t(*)[SMEM_STRIDE])sm;
    uint32_t (*Vs)[SMEM_STRIDE] = (uint32_t(*)[SMEM_STRIDE])(sm + 128 * SMEM_STRIDE);
    int z = blockIdx.y;
    int b = z >> 4, n = z & (NH - 1);
    const float* P = cov + (size_t)z * QLEN * KLEN;
    const float* Vm = g_V + (size_t)z * KLEN * DH;
    int row0 = blockIdx.x * 128;
    int tid = threadIdx.x;
    int wid = tid >> 5, lane = tid & 31, g = lane >> 2, t = lane & 3;
    int wm = (wid & 3) * 32, wn = (wid >> 2) * 32;
    float c[2][4][4] = {};
    for (int kc = 0; kc < KLEN; kc += 64) {
#pragma unroll
        for (int i = 0; i < 8; i++) {
            int f4 = tid + i * 256;
            int rw = f4 >> 4, c4 = (f4 & 15) * 4;
            float4 v = *(const float4*)&P[(size_t)(row0 + rw) * KLEN + kc + c4];
            *(uint4*)&Ps[rw][c4] = make_uint4(f2tf(v.x), f2tf(v.y), f2tf(v.z), f2tf(v.w));
        }
#pragma unroll
        for (int i = 0; i < 4; i++) {
            int f4 = tid + i * 256;
            int rw = f4 >> 4, c4 = (f4 & 15) * 4;
            float4 v = *(const float4*)&Vm[(size_t)(kc + rw) * DH + c4];
            *(uint4*)&Vs[rw][c4] = make_uint4(f2tf(v.x), f2tf(v.y), f2tf(v.z), f2tf(v.w));
        }
        __syncthreads();
#pragma unroll
        for (int k0 = 0; k0 < 64; k0 += 8) {
            uint32_t a[2][4], b2[4][2];
#pragma unroll
            for (int mt = 0; mt < 2; mt++) {
                int r = wm + mt * 16 + g;
                a[mt][0] = Ps[r][k0 + t];     a[mt][1] = Ps[r + 8][k0 + t];
                a[mt][2] = Ps[r][k0 + t + 4]; a[mt][3] = Ps[r + 8][k0 + t + 4];
            }
#pragma unroll
            for (int nt = 0; nt < 4; nt++) {
                int cn = wn + nt * 8 + g;
                b2[nt][0] = Vs[k0 + t][cn];
                b2[nt][1] = Vs[k0 + t + 4][cn];
            }
#pragma unroll
            for (int mt = 0; mt < 2; mt++)
#pragma unroll
                for (int nt = 0; nt < 4; nt++) mma8(c[mt][nt], a[mt], b2[nt]);
        }
        __syncthreads();
    }
#pragma unroll
    for (int mt = 0; mt < 2; mt++) {
        int q0 = row0 + wm + mt * 16 + g;
#pragma unroll
        for (int nt = 0; nt < 4; nt++) {
            int d = wn + nt * 8 + 2 * t;
#pragma unroll
            for (int rr = 0; rr < 2; rr++) {
                int q = q0 + rr * 8;
                float2 v;
                v.x = c[mt][nt][rr * 2 + 0];
                v.y = c[mt][nt][rr * 2 + 1];
                *(float2*)&g_AV[((size_t)q * BSZ + b) * DM + n * DH + d] = v;
            }
        }
    }
}

// ---------------- launch ------------------------------------------------------
extern "C" void kernel_launch(void* const* d_in, const int* in_sizes, int n_in,
                              void* d_out, int out_size) {
    const float* w       = (const float*)d_in[0];
    const float* r       = (const float*)d_in[1];
    const void*  mask    = d_in[2];
    const float* qkv_w   = (const float*)d_in[3];
    const float* r_net_w = (const float*)d_in[4];
    const float* o_w     = (const float*)d_in[5];
    const float* r_r_bias = (const float*)d_in[7];  // reference bug: r_r_bias for both

    float* out = (float*)d_out;
    float* cov = out + (size_t)QLEN * BSZ * DM;

    const int SMEM_FUSED = (BD_WORDS + (129 + 128) * SMEM_STRIDE) * 4;  // 203024
    const int SMEM_PV    = (128 + 64) * SMEM_STRIDE * 4;                // 52224
    static int attr_done = 0;
    if (!attr_done) {
        cudaFuncSetAttribute(score_fused_kernel, cudaFuncAttributeMaxDynamicSharedMemorySize, SMEM_FUSED);
        cudaFuncSetAttribute(pv_mma_kernel,      cudaFuncAttributeMaxDynamicSharedMemorySize, SMEM_PV);
        attr_done = 1;
    }

    mask_expand_kernel<<<1, 256>>>((const unsigned char*)mask);
    gemm_qkv_kernel<<<dim3(24, 32), 256>>>(w, qkv_w, r_r_bias);
    gemm_rnet_kernel<<<dim3(8, 16), 256>>>(r, r_net_w);
    score_fused_kernel<<<dim3(4, 16, BSZ * NH), 512, SMEM_FUSED>>>(cov);
    softmax_kernel<<<BSZ * NH * QLEN, 256>>>(cov);
    pv_mma_kernel<<<dim3(16, BSZ * NH), 256, SMEM_PV>>>(cov);
    gemm_out_kernel<<<dim3(8, 32), 256>>>(o_w, out);
}

// round 14
// speedup vs baseline: 1.0066x; 1.0066x over previous
#include <cuda_runtime.h>
#include <cuda_bf16.h>
#include <math.h>
#include <stdint.h>

#define QLEN  2048
#define BSZ   2
#define NH    16
#define DH    64
#define DM    1024
#define KLEN  2048
#define RLEN  2048
// 0.125 * log2(e): scores stored in base-2 domain so softmax uses 2^x
#define SCALE_L2E 0.1803368801111244f

// ---------------- scratch (device globals) ----------------------------------
__device__ float g_Qb[(size_t)BSZ * NH * QLEN * DH];   // Q + r_r_bias, (b,n,q,d)
__device__ float g_K [(size_t)BSZ * NH * KLEN * DH];   // (b,n,k,d)
__device__ float g_V [(size_t)BSZ * NH * KLEN * DH];   // (b,n,k,d)
__device__ float g_Rk[(size_t)NH * RLEN * DH];         // (n,r,d)
__device__ float g_AV[(size_t)QLEN * BSZ * DM];        // attn_vec (q,b,n*d)
__device__ float g_negmask[(size_t)BSZ * KLEN];        // 0 or -inf, [b][k]

// ---------------- helpers -----------------------------------------------------
__device__ __forceinline__ uint32_t f2tf(float f) {
    uint32_t u; asm("cvt.rna.tf32.f32 %0, %1;" : "=r"(u) : "f"(f)); return u;
}
__device__ __forceinline__ void mma8(float* c, const uint32_t* a, const uint32_t* b) {
    asm volatile(
        "mma.sync.aligned.m16n8k8.row.col.f32.tf32.tf32.f32 "
        "{%0,%1,%2,%3}, {%4,%5,%6,%7}, {%8,%9}, {%0,%1,%2,%3};"
        : "+f"(c[0]), "+f"(c[1]), "+f"(c[2]), "+f"(c[3])
        : "r"(a[0]), "r"(a[1]), "r"(a[2]), "r"(a[3]), "r"(b[0]), "r"(b[1]));
}
__device__ __forceinline__ void ldsm4(uint32_t &r0, uint32_t &r1, uint32_t &r2, uint32_t &r3,
                                      uint32_t addr) {
    asm volatile("ldmatrix.sync.aligned.m8n8.x4.shared.b16 {%0,%1,%2,%3}, [%4];"
        : "=r"(r0), "=r"(r1), "=r"(r2), "=r"(r3) : "r"(addr));
}
// branch-free 2^t on FMA/ALU pipes. t <= 0 expected; -inf -> ~0.
__device__ __forceinline__ float fexp2(float t) {
    t = fmaxf(t, -126.0f);
    float u = t + 12582912.0f;
    int ki = __float_as_int(u) - 0x4B400000;
    float fk = u - 12582912.0f;
    float f = t - fk;
    float p = 0.0013333558f;
    p = fmaf(p, f, 0.0096181291f);
    p = fmaf(p, f, 0.0555041087f);
    p = fmaf(p, f, 0.2402265069f);
    p = fmaf(p, f, 0.6931471806f);
    p = fmaf(p, f, 1.0f);
    return __int_as_float(__float_as_int(p) + (ki << 23));
}

// ---------------- mask detect + expand (validated) ---------------------------
__global__ void mask_expand_kernel(const unsigned char* __restrict__ m) {
    __shared__ int cnt[4];
    __shared__ int smode;
    if (threadIdx.x < 4) cnt[threadIdx.x] = 0;
    __syncthreads();
    for (int i = threadIdx.x; i < 4096; i += blockDim.x)
        if (m[i]) atomicAdd(&cnt[i & 3], 1);
    __syncthreads();
    if (threadIdx.x == 0) {
        int mode;
        if (cnt[1] == 0 && cnt[2] == 0 && cnt[3] == 0) mode = 0;      // int32
        else if (cnt[0] == 0 && cnt[1] == 0)           mode = 1;      // float32
        else                                           mode = 2;      // bool byte
        smode = mode;
    }
    __syncthreads();
    int mode = smode;
    for (int idx = threadIdx.x; idx < KLEN * BSZ; idx += blockDim.x) {
        bool msk;
        if (mode == 0)      msk = ((const int*)m)[idx] != 0;
        else if (mode == 1) msk = ((const float*)m)[idx] != 0.0f;
        else                msk = m[idx] != 0;
        int k = idx >> 1, b = idx & 1;
        g_negmask[b * KLEN + k] = msk ? -INFINITY : 0.0f;
    }
}

// =============================================================================
// NN TF32 MMA GEMM body (validated round 6)
// =============================================================================
#define NN_TF32_BODY(Aptr, Bptr, Kdim, Ndim, ...)                               \
    __shared__ uint32_t As[128][36];                                            \
    __shared__ uint32_t Bs[32][136];                                            \
    int tid = threadIdx.x;                                                      \
    int row0 = blockIdx.y * 128, col0 = blockIdx.x * 128;                       \
    int wid = tid >> 5, lane = tid & 31, g = lane >> 2, t = lane & 3;           \
    int wm = (wid & 3) * 32, wn = (wid >> 2) * 64;                              \
    (void)lane;                                                                 \
    float c[2][8][4] = {};                                                      \
    float4 pa[4], pb[4];                                                        \
    _Pragma("unroll")                                                           \
    for (int i = 0; i < 4; i++) {                                               \
        int f4 = tid + i * 256;                                                 \
        int rw = f4 >> 3, c4 = (f4 & 7) * 4;                                    \
        pa[i] = *(const float4*)&Aptr[(size_t)(row0 + rw) * Kdim + c4];         \
        int brw = f4 >> 5, bc4 = (f4 & 31) * 4;                                 \
        pb[i] = *(const float4*)&Bptr[(size_t)brw * Ndim + col0 + bc4];         \
    }                                                                           \
    for (int k0c = 0; k0c < Kdim; k0c += 32) {                                  \
        _Pragma("unroll")                                                       \
        for (int i = 0; i < 4; i++) {                                           \
            int f4 = tid + i * 256;                                             \
            int rw = f4 >> 3, c4 = (f4 & 7) * 4;                                \
            *(uint4*)&As[rw][c4] =                                              \
                make_uint4(f2tf(pa[i].x), f2tf(pa[i].y), f2tf(pa[i].z), f2tf(pa[i].w)); \
            int brw = f4 >> 5, bc4 = (f4 & 31) * 4;                             \
            *(uint4*)&Bs[brw][bc4] =                                            \
                make_uint4(f2tf(pb[i].x), f2tf(pb[i].y), f2tf(pb[i].z), f2tf(pb[i].w)); \
        }                                                                       \
        __syncthreads();                                                        \
        if (k0c + 32 < Kdim) {                                                  \
            _Pragma("unroll")                                                   \
            for (int i = 0; i < 4; i++) {                                       \
                int f4 = tid + i * 256;                                         \
                int rw = f4 >> 3, c4 = (f4 & 7) * 4;                            \
                pa[i] = *(const float4*)&Aptr[(size_t)(row0 + rw) * Kdim + k0c + 32 + c4]; \
                int brw = f4 >> 5, bc4 = (f4 & 31) * 4;                         \
                pb[i] = *(const float4*)&Bptr[(size_t)(k0c + 32 + brw) * Ndim + col0 + bc4]; \
            }                                                                   \
        }                                                                       \
        _Pragma("unroll")                                                       \
        for (int k0 = 0; k0 < 32; k0 += 8) {                                    \
            uint32_t a[2][4], b2[8][2];                                         \
            _Pragma("unroll")                                                   \
            for (int mt = 0; mt < 2; mt++) {                                    \
                int r = wm + mt * 16 + g;                                       \
                a[mt][0] = As[r][k0 + t];     a[mt][1] = As[r + 8][k0 + t];     \
                a[mt][2] = As[r][k0 + t + 4]; a[mt][3] = As[r + 8][k0 + t + 4]; \
            }                                                                   \
            _Pragma("unroll")                                                   \
            for (int nt = 0; nt < 8; nt++) {                                    \
                int cn = wn + nt * 8 + g;                                       \
                b2[nt][0] = Bs[k0 + t][cn];                                     \
                b2[nt][1] = Bs[k0 + t + 4][cn];                                 \
            }                                                                   \
            _Pragma("unroll")                                                   \
            for (int mt = 0; mt < 2; mt++)                                      \
                _Pragma("unroll")                                               \
                for (int nt = 0; nt < 8; nt++) mma8(c[mt][nt], a[mt], b2[nt]);  \
        }                                                                       \
        __syncthreads();                                                        \
    }                                                                           \
    __VA_ARGS__

// ---------------- GEMM 1: heads = w @ qkv_w -> Qb/K/V (TF32) -----------------
__global__ __launch_bounds__(256)
void gemm_qkv_kernel(const float* __restrict__ A, const float* __restrict__ B,
                     const float* __restrict__ rbias) {
    NN_TF32_BODY(A, B, 1024, 3072, {
        for (int mt = 0; mt < 2; mt++) {
            for (int rr = 0; rr < 2; rr++) {
                int m = row0 + wm + mt * 16 + g + rr * 8;
                int q = m >> 1;
                int bb = m & 1;
                for (int nt = 0; nt < 8; nt++) {
                    int cc = col0 + wn + nt * 8 + 2 * t;
                    int sec = cc >> 10;
                    int h = (cc & 1023) >> 6;
                    int d = cc & 63;
                    size_t off = ((size_t)(bb * NH + h) * QLEN + q) * DH + d;
                    float vx = c[mt][nt][rr * 2 + 0];
                    float vy = c[mt][nt][rr * 2 + 1];
                    if (sec == 0) {
                        float2 rb = *(const float2*)&rbias[h * 64 + d];
                        float2 v;
                        v.x = vx + rb.x;
                        v.y = vy + rb.y;
                        *(float2*)&g_Qb[off] = v;
                    } else if (sec == 1) {
                        float2 v; v.x = vx; v.y = vy;
                        *(float2*)&g_K[off] = v;
                    } else {
                        float2 v; v.x = vx; v.y = vy;
                        *(float2*)&g_V[off] = v;
                    }
                }
            }
        }
    })
}

// ---------------- GEMM 2: r_head_k = r @ r_net_w -> Rk (TF32) ----------------
__global__ __launch_bounds__(256)
void gemm_rnet_kernel(const float* __restrict__ A, const float* __restrict__ B) {
    NN_TF32_BODY(A, B, 1024, 1024, {
        for (int mt = 0; mt < 2; mt++) {
            for (int rr = 0; rr < 2; rr++) {
                int m = row0 + wm + mt * 16 + g + rr * 8;
                for (int nt = 0; nt < 8; nt++) {
                    int cc = col0 + wn + nt * 8 + 2 * t;
                    int h = cc >> 6;
                    int d = cc & 63;
                    float2 v;
                    v.x = c[mt][nt][rr * 2 + 0];
                    v.y = c[mt][nt][rr * 2 + 1];
                    *(float2*)&g_Rk[((size_t)h * RLEN + m) * DH + d] = v;
                }
            }
        }
    })
}

// ---------------- GEMM 6: output = attn_vec @ o_w (TF32) ---------------------
__global__ __launch_bounds__(256)
void gemm_out_kernel(const float* __restrict__ B, float* __restrict__ out) {
    const float* A = g_AV;
    NN_TF32_BODY(A, B, 1024, 1024, {
        for (int mt = 0; mt < 2; mt++) {
            for (int rr = 0; rr < 2; rr++) {
                int m = row0 + wm + mt * 16 + g + rr * 8;
                for (int nt = 0; nt < 8; nt++) {
                    int cc = col0 + wn + nt * 8 + 2 * t;
                    float2 v;
                    v.x = c[mt][nt][rr * 2 + 0];
                    v.y = c[mt][nt][rr * 2 + 1];
                    *(float2*)&out[(size_t)m * 1024 + cc] = v;
                }
            }
        }
    })
}

// =============================================================================
// Fused score kernel: 512 threads, 129-row Q buffer (band qoff via +1 row
// index; validated r13), one 128-col tile per CTA (grid 16,16,32; r11 layout),
// LDSM (ldmatrix.x4) fragment fetches.
// SMEM: BDs[128][260] | Qs[129][68] | Ks[128][68]
// =============================================================================
#define SMEM_STRIDE 68
#define BD_STRIDE 260
#define BD_WORDS (128 * BD_STRIDE)

__global__ __launch_bounds__(512, 1)
void score_fused_kernel(float* __restrict__ cov) {
    extern __shared__ uint32_t sm[];
    float* BDs = (float*)sm;                                   // 128 x 260 floats
    uint32_t (*Qs)[SMEM_STRIDE] = (uint32_t(*)[SMEM_STRIDE])(sm + BD_WORDS);            // 129 rows
    uint32_t (*Ks)[SMEM_STRIDE] = (uint32_t(*)[SMEM_STRIDE])(sm + BD_WORDS + 129 * SMEM_STRIDE);

    int z = blockIdx.z;
    int b = z >> 4;
    int n = z & (NH - 1);
    const float* Qp  = g_Qb + (size_t)z * QLEN * DH;
    const float* Kp  = g_K  + (size_t)z * KLEN * DH;
    const float* Rkn = g_Rk + (size_t)n * RLEN * DH;
    int row0 = blockIdx.y * 128, col0 = blockIdx.x * 128;
    int tid = threadIdx.x;
    int wid = tid >> 5, lane = tid & 31, g = lane >> 2, t = lane & 3;
    int wm = (wid & 3) * 32, wn = (wid >> 2) * 32;   // 4x4 warp grid, 32x32 tiles

    // LDSM lane-address components (derived + bank-rotation verified)
    uint32_t QsBase = (uint32_t)__cvta_generic_to_shared(&Qs[0][0]);
    uint32_t KsBase = (uint32_t)__cvta_generic_to_shared(&Ks[0][0]);
    int rowA = (lane & 7) + ((lane >> 3) & 1) * 8;   // A: m0/m1 row halves
    int colA = (lane >> 4) * 4;                      // A: m2/m3 k halves
    int rowB = (lane & 7) + (lane >> 4) * 8;         // B: nt / nt+1 rows
    int colB = ((lane >> 3) & 1) * 4;                // B: k halves

    // ---- load Q once: rows row0..row0+128 (129 rows; last clamped) ----
#pragma unroll
    for (int i = 0; i < 4; i++) {
        int f4 = tid + i * 512;
        int rw = f4 >> 4, c4 = (f4 & 15) * 4;
        float4 qa = *(const float4*)&Qp[(size_t)(row0 + rw) * DH + c4];
        *(uint4*)&Qs[rw][c4] = make_uint4(f2tf(qa.x), f2tf(qa.y), f2tf(qa.z), f2tf(qa.w));
    }
    if (tid < 16) {
        int qr = row0 + 128; if (qr > 2047) qr = 2047;
        int c4 = tid * 4;
        float4 qa = *(const float4*)&Qp[(size_t)qr * DH + c4];
        *(uint4*)&Qs[128][c4] = make_uint4(f2tf(qa.x), f2tf(qa.y), f2tf(qa.z), f2tf(qa.w));
    }
    // ---- K tile load ----
#pragma unroll
    for (int i = 0; i < 4; i++) {
        int f4 = tid + i * 512;
        int rw = f4 >> 4, c4 = (f4 & 15) * 4;
        float4 kb = *(const float4*)&Kp[(size_t)(col0 + rw) * DH + c4];
        *(uint4*)&Ks[rw][c4] = make_uint4(f2tf(kb.x), f2tf(kb.y), f2tf(kb.z), f2tf(kb.w));
    }
    __syncthreads();

    // ---- AC MMA (LDSM fragments) ----
    float c[2][4][4] = {};
#pragma unroll
    for (int k0 = 0; k0 < 64; k0 += 8) {
        uint32_t a[2][4], b2[4][2];
#pragma unroll
        for (int mt = 0; mt < 2; mt++)
            ldsm4(a[mt][0], a[mt][1], a[mt][2], a[mt][3],
                  QsBase + (((wm + mt * 16 + rowA) * SMEM_STRIDE + k0 + colA) << 2));
#pragma unroll
        for (int ntp = 0; ntp < 2; ntp++)
            ldsm4(b2[2 * ntp][0], b2[2 * ntp][1], b2[2 * ntp + 1][0], b2[2 * ntp + 1][1],
                  KsBase + (((wn + ntp * 16 + rowB) * SMEM_STRIDE + k0 + colB) << 2));
#pragma unroll
        for (int mt = 0; mt < 2; mt++)
#pragma unroll
            for (int nt = 0; nt < 4; nt++) mma8(c[mt][nt], a[mt], b2[nt]);
    }
    __syncthreads();   // AC done; Ks reusable

    // ---- band parameters (validated round 10/13) ----
    int below = (col0 < row0);
    int diag  = (col0 == row0);
    int d0 = col0 - row0;
    int qoffA   = (below || diag) ? 0 : 1;
    int rstartA = (below || diag) ? (1920 + d0) : (d0 - 129);
    int qoffB   = below ? 0 : 1;
    int rstartB = below ? (1920 + d0 + 128) : (diag ? -1 : (d0 - 129 + 128));

#pragma unroll 1
    for (int half = 0; half < 2; half++) {
        int qoff   = half ? qoffB : qoffA;
        int rstart = half ? rstartB : rstartA;
#pragma unroll
        for (int i = 0; i < 4; i++) {
            int f4 = tid + i * 512;
            int rw = f4 >> 4, c4 = (f4 & 15) * 4;
            int rr_ = rstart + rw; if (rr_ < 0) rr_ = 0; if (rr_ > 2047) rr_ = 2047;
            float4 kb = *(const float4*)&Rkn[(size_t)rr_ * DH + c4];
            *(uint4*)&Ks[rw][c4] = make_uint4(f2tf(kb.x), f2tf(kb.y), f2tf(kb.z), f2tf(kb.w));
        }
        __syncthreads();
        float c2[2][4][4] = {};
#pragma unroll
        for (int k0 = 0; k0 < 64; k0 += 8) {
            uint32_t a[2][4], b2[4][2];
#pragma unroll
            for (int mt = 0; mt < 2; mt++)
                ldsm4(a[mt][0], a[mt][1], a[mt][2], a[mt][3],
                      QsBase + (((wm + mt * 16 + qoff + rowA) * SMEM_STRIDE + k0 + colA) << 2));
#pragma unroll
            for (int ntp = 0; ntp < 2; ntp++)
                ldsm4(b2[2 * ntp][0], b2[2 * ntp][1], b2[2 * ntp + 1][0], b2[2 * ntp + 1][1],
                      KsBase + (((wn + ntp * 16 + rowB) * SMEM_STRIDE + k0 + colB) << 2));
#pragma unroll
            for (int mt = 0; mt < 2; mt++)
#pragma unroll
                for (int nt = 0; nt < 4; nt++) mma8(c2[mt][nt], a[mt], b2[nt]);
        }
        // stage raw half into BDs columns [half*128, half*128+128)
#pragma unroll
        for (int mt = 0; mt < 2; mt++)
#pragma unroll
            for (int nt = 0; nt < 4; nt++)
#pragma unroll
                for (int rr = 0; rr < 2; rr++) {
                    int r = wm + mt * 16 + g + rr * 8;
                    int ccol = half * 128 + wn + nt * 8 + 2 * t;
                    float2 v;
                    v.x = c2[mt][nt][rr * 2 + 0];
                    v.y = c2[mt][nt][rr * 2 + 1];
                    *(float2*)&BDs[r * BD_STRIDE + ccol] = v;
                }
        __syncthreads();
    }

    // ---- epilogue: s = (AC + BDs[qi][127+ki-qi]) * scale + negmask ----
    const float* neg = g_negmask + (size_t)b * KLEN;
    float* Cz = cov + (size_t)z * QLEN * KLEN;
#pragma unroll
    for (int mt = 0; mt < 2; mt++) {
        int qi0 = wm + mt * 16 + g;
#pragma unroll
        for (int nt = 0; nt < 4; nt++) {
            int kloc = wn + nt * 8 + 2 * t;
            int kb = col0 + kloc;
            float2 ng = *(const float2*)&neg[kb];
#pragma unroll
            for (int rr = 0; rr < 2; rr++) {
                int qi = qi0 + rr * 8;
                int q = row0 + qi;
                int jj = 127 + kloc - qi;
                float bdx = (kb     == q + 1) ? 0.0f : BDs[qi * BD_STRIDE + jj];
                float bdy = (kb + 1 == q + 1) ? 0.0f : BDs[qi * BD_STRIDE + jj + 1];
                float2 s;
                s.x = (c[mt][nt][rr * 2 + 0] + bdx) * SCALE_L2E + ng.x;
                s.y = (c[mt][nt][rr * 2 + 1] + bdy) * SCALE_L2E + ng.y;
                *(float2*)&Cz[(size_t)q * KLEN + kb] = s;
            }
        }
    }
}

// ---------------- softmax over k (validated; base-2 domain) ------------------
__global__ __launch_bounds__(256)
void softmax_kernel(float* __restrict__ cov) {
    size_t row = blockIdx.x;
    float* p = cov + row * KLEN;
    int t = threadIdx.x;
    float4 v0 = ((const float4*)p)[t];
    float4 v1 = ((const float4*)p)[t + 256];
    float m = fmaxf(fmaxf(fmaxf(v0.x, v0.y), fmaxf(v0.z, v0.w)),
                    fmaxf(fmaxf(v1.x, v1.y), fmaxf(v1.z, v1.w)));
    __shared__ float sred[8];
#pragma unroll
    for (int o = 16; o; o >>= 1) m = fmaxf(m, __shfl_xor_sync(0xffffffffu, m, o));
    if ((t & 31) == 0) sred[t >> 5] = m;
    __syncthreads();
    if (t < 8) {
        float x = sred[t];
#pragma unroll
        for (int o = 4; o; o >>= 1) x = fmaxf(x, __shfl_xor_sync(0xffu, x, o));
        if (t == 0) sred[0] = x;
    }
    __syncthreads();
    m = sred[0];
    if (m == -INFINITY) {   // fully-masked row -> 0 per reference
        float4 zz = make_float4(0.f, 0.f, 0.f, 0.f);
        ((float4*)p)[t] = zz;
        ((float4*)p)[t + 256] = zz;
        return;
    }
    float e0x = fexp2(v0.x - m), e0y = fexp2(v0.y - m);
    float e0z = fexp2(v0.z - m), e0w = fexp2(v0.w - m);
    float e1x = fexp2(v1.x - m), e1y = fexp2(v1.y - m);
    float e1z = fexp2(v1.z - m), e1w = fexp2(v1.w - m);
    float s = (e0x + e0y) + (e0z + e0w) + (e1x + e1y) + (e1z + e1w);
    __shared__ float ssum[8];
#pragma unroll
    for (int o = 16; o; o >>= 1) s += __shfl_xor_sync(0xffffffffu, s, o);
    if ((t & 31) == 0) ssum[t >> 5] = s;
    __syncthreads();
    if (t < 8) {
        float x = ssum[t];
#pragma unroll
        for (int o = 4; o; o >>= 1) x += __shfl_xor_sync(0xffu, x, o);
        if (t == 0) ssum[0] = x;
    }
    __syncthreads();
    float inv = 1.0f / ssum[0];
    ((float4*)p)[t]       = make_float4(e0x * inv, e0y * inv, e0z * inv, e0w * inv);
    ((float4*)p)[t + 256] = make_float4(e1x * inv, e1y * inv, e1z * inv, e1w * inv);
}

// ---------------- PV: attn_vec = P @ V (TF32 MMA, validated r6) --------------
__global__ __launch_bounds__(256)
void pv_mma_kernel(const float* __restrict__ cov) {
    extern __shared__ uint32_t sm[];
    uint32_t (*Ps)[SMEM_STRIDE] = (uint32_t(*)[SMEM_STRIDE])sm;
    uint32_t (*Vs)[SMEM_STRIDE] = (uint32_t(*)[SMEM_STRIDE])(sm + 128 * SMEM_STRIDE);
    int z = blockIdx.y;
    int b = z >> 4, n = z & (NH - 1);
    const float* P = cov + (size_t)z * QLEN * KLEN;
    const float* Vm = g_V + (size_t)z * KLEN * DH;
    int row0 = blockIdx.x * 128;
    int tid = threadIdx.x;
    int wid = tid >> 5, lane = tid & 31, g = lane >> 2, t = lane & 3;
    int wm = (wid & 3) * 32, wn = (wid >> 2) * 32;
    float c[2][4][4] = {};
    for (int kc = 0; kc < KLEN; kc += 64) {
#pragma unroll
        for (int i = 0; i < 8; i++) {
            int f4 = tid + i * 256;
            int rw = f4 >> 4, c4 = (f4 & 15) * 4;
            float4 v = *(const float4*)&P[(size_t)(row0 + rw) * KLEN + kc + c4];
            *(uint4*)&Ps[rw][c4] = make_uint4(f2tf(v.x), f2tf(v.y), f2tf(v.z), f2tf(v.w));
        }
#pragma unroll
        for (int i = 0; i < 4; i++) {
            int f4 = tid + i * 256;
            int rw = f4 >> 4, c4 = (f4 & 15) * 4;
            float4 v = *(const float4*)&Vm[(size_t)(kc + rw) * DH + c4];
            *(uint4*)&Vs[rw][c4] = make_uint4(f2tf(v.x), f2tf(v.y), f2tf(v.z), f2tf(v.w));
        }
        __syncthreads();
#pragma unroll
        for (int k0 = 0; k0 < 64; k0 += 8) {
            uint32_t a[2][4], b2[4][2];
#pragma unroll
            for (int mt = 0; mt < 2; mt++) {
                int r = wm + mt * 16 + g;
                a[mt][0] = Ps[r][k0 + t];     a[mt][1] = Ps[r + 8][k0 + t];
                a[mt][2] = Ps[r][k0 + t + 4]; a[mt][3] = Ps[r + 8][k0 + t + 4];
            }
#pragma unroll
            for (int nt = 0; nt < 4; nt++) {
                int cn = wn + nt * 8 + g;
                b2[nt][0] = Vs[k0 + t][cn];
                b2[nt][1] = Vs[k0 + t + 4][cn];
            }
#pragma unroll
            for (int mt = 0; mt < 2; mt++)
#pragma unroll
                for (int nt = 0; nt < 4; nt++) mma8(c[mt][nt], a[mt], b2[nt]);
        }
        __syncthreads();
    }
#pragma unroll
    for (int mt = 0; mt < 2; mt++) {
        int q0 = row0 + wm + mt * 16 + g;
#pragma unroll
        for (int nt = 0; nt < 4; nt++) {
            int d = wn + nt * 8 + 2 * t;
#pragma unroll
            for (int rr = 0; rr < 2; rr++) {
                int q = q0 + rr * 8;
                float2 v;
                v.x = c[mt][nt][rr * 2 + 0];
                v.y = c[mt][nt][rr * 2 + 1];
                *(float2*)&g_AV[((size_t)q * BSZ + b) * DM + n * DH + d] = v;
            }
        }
    }
}

// ---------------- launch ------------------------------------------------------
extern "C" void kernel_launch(void* const* d_in, const int* in_sizes, int n_in,
                              void* d_out, int out_size) {
    const float* w       = (const float*)d_in[0];
    const float* r       = (const float*)d_in[1];
    const void*  mask    = d_in[2];
    const float* qkv_w   = (const float*)d_in[3];
    const float* r_net_w = (const float*)d_in[4];
    const float* o_w     = (const float*)d_in[5];
    const float* r_r_bias = (const float*)d_in[7];  // reference bug: r_r_bias for both

    float* out = (float*)d_out;
    float* cov = out + (size_t)QLEN * BSZ * DM;

    const int SMEM_FUSED = (BD_WORDS + (129 + 128) * SMEM_STRIDE) * 4;  // 203024
    const int SMEM_PV    = (128 + 64) * SMEM_STRIDE * 4;                // 52224
    static int attr_done = 0;
    if (!attr_done) {
        cudaFuncSetAttribute(score_fused_kernel, cudaFuncAttributeMaxDynamicSharedMemorySize, SMEM_FUSED);
        cudaFuncSetAttribute(pv_mma_kernel,      cudaFuncAttributeMaxDynamicSharedMemorySize, SMEM_PV);
        attr_done = 1;
    }

    mask_expand_kernel<<<1, 256>>>((const unsigned char*)mask);
    gemm_qkv_kernel<<<dim3(24, 32), 256>>>(w, qkv_w, r_r_bias);
    gemm_rnet_kernel<<<dim3(8, 16), 256>>>(r, r_net_w);
    score_fused_kernel<<<dim3(16, 16, BSZ * NH), 512, SMEM_FUSED>>>(cov);
    softmax_kernel<<<BSZ * NH * QLEN, 256>>>(cov);
    pv_mma_kernel<<<dim3(16, BSZ * NH), 256, SMEM_PV>>>(cov);
    gemm_out_kernel<<<dim3(8, 32), 256>>>(o_w, out);
}

// round 15
// speedup vs baseline: 1.4872x; 1.4775x over previous
#include <cuda_runtime.h>
#include <cuda_bf16.h>
#include <math.h>
#include <stdint.h>

#define QLEN  2048
#define BSZ   2
#define NH    16
#define DH    64
#define DM    1024
#define KLEN  2048
#define RLEN  2048
// 0.125 * log2(e): scores stored in base-2 domain so softmax uses 2^x
#define SCALE_L2E 0.1803368801111244f

// ---------------- scratch (device globals) ----------------------------------
__device__ float g_Qb[(size_t)BSZ * NH * QLEN * DH];   // Q + r_r_bias, (b,n,q,d)
__device__ float g_K [(size_t)BSZ * NH * KLEN * DH];   // (b,n,k,d)
__device__ float g_V [(size_t)BSZ * NH * KLEN * DH];   // (b,n,k,d)
__device__ float g_Rk[(size_t)NH * RLEN * DH];         // (n,r,d)
__device__ float g_AV[(size_t)QLEN * BSZ * DM];        // attn_vec (q,b,n*d)
__device__ float g_negmask[(size_t)BSZ * KLEN];        // 0 or -inf, [b][k]

// ---------------- helpers -----------------------------------------------------
__device__ __forceinline__ uint32_t f2tf(float f) {
    uint32_t u; asm("cvt.rna.tf32.f32 %0, %1;" : "=r"(u) : "f"(f)); return u;
}
__device__ __forceinline__ void mma8(float* c, const uint32_t* a, const uint32_t* b) {
    asm volatile(
        "mma.sync.aligned.m16n8k8.row.col.f32.tf32.tf32.f32 "
        "{%0,%1,%2,%3}, {%4,%5,%6,%7}, {%8,%9}, {%0,%1,%2,%3};"
        : "+f"(c[0]), "+f"(c[1]), "+f"(c[2]), "+f"(c[3])
        : "r"(a[0]), "r"(a[1]), "r"(a[2]), "r"(a[3]), "r"(b[0]), "r"(b[1]));
}
// branch-free 2^t on FMA/ALU pipes. t <= 0 expected; -inf -> ~0.
__device__ __forceinline__ float fexp2(float t) {
    t = fmaxf(t, -126.0f);
    float u = t + 12582912.0f;
    int ki = __float_as_int(u) - 0x4B400000;
    float fk = u - 12582912.0f;
    float f = t - fk;
    float p = 0.0013333558f;
    p = fmaf(p, f, 0.0096181291f);
    p = fmaf(p, f, 0.0555041087f);
    p = fmaf(p, f, 0.2402265069f);
    p = fmaf(p, f, 0.6931471806f);
    p = fmaf(p, f, 1.0f);
    return __int_as_float(__float_as_int(p) + (ki << 23));
}

// ---------------- mask detect + expand (validated) ---------------------------
__global__ void mask_expand_kernel(const unsigned char* __restrict__ m) {
    __shared__ int cnt[4];
    __shared__ int smode;
    if (threadIdx.x < 4) cnt[threadIdx.x] = 0;
    __syncthreads();
    for (int i = threadIdx.x; i < 4096; i += blockDim.x)
        if (m[i]) atomicAdd(&cnt[i & 3], 1);
    __syncthreads();
    if (threadIdx.x == 0) {
        int mode;
        if (cnt[1] == 0 && cnt[2] == 0 && cnt[3] == 0) mode = 0;      // int32
        else if (cnt[0] == 0 && cnt[1] == 0)           mode = 1;      // float32
        else                                           mode = 2;      // bool byte
        smode = mode;
    }
    __syncthreads();
    int mode = smode;
    for (int idx = threadIdx.x; idx < KLEN * BSZ; idx += blockDim.x) {
        bool msk;
        if (mode == 0)      msk = ((const int*)m)[idx] != 0;
        else if (mode == 1) msk = ((const float*)m)[idx] != 0.0f;
        else                msk = m[idx] != 0;
        int k = idx >> 1, b = idx & 1;
        g_negmask[b * KLEN + k] = msk ? -INFINITY : 0.0f;
    }
}

// =============================================================================
// NN TF32 MMA GEMM body (validated round 6)
// =============================================================================
#define NN_TF32_BODY(Aptr, Bptr, Kdim, Ndim, ...)                               \
    __shared__ uint32_t As[128][36];                                            \
    __shared__ uint32_t Bs[32][136];                                            \
    int tid = threadIdx.x;                                                      \
    int row0 = blockIdx.y * 128, col0 = blockIdx.x * 128;                       \
    int wid = tid >> 5, lane = tid & 31, g = lane >> 2, t = lane & 3;           \
    int wm = (wid & 3) * 32, wn = (wid >> 2) * 64;                              \
    (void)lane;                                                                 \
    float c[2][8][4] = {};                                                      \
    float4 pa[4], pb[4];                                                        \
    _Pragma("unroll")                                                           \
    for (int i = 0; i < 4; i++) {                                               \
        int f4 = tid + i * 256;                                                 \
        int rw = f4 >> 3, c4 = (f4 & 7) * 4;                                    \
        pa[i] = *(const float4*)&Aptr[(size_t)(row0 + rw) * Kdim + c4];         \
        int brw = f4 >> 5, bc4 = (f4 & 31) * 4;                                 \
        pb[i] = *(const float4*)&Bptr[(size_t)brw * Ndim + col0 + bc4];         \
    }                                                                           \
    for (int k0c = 0; k0c < Kdim; k0c += 32) {                                  \
        _Pragma("unroll")                                                       \
        for (int i = 0; i < 4; i++) {                                           \
            int f4 = tid + i * 256;                                             \
            int rw = f4 >> 3, c4 = (f4 & 7) * 4;                                \
            *(uint4*)&As[rw][c4] =                                              \
                make_uint4(f2tf(pa[i].x), f2tf(pa[i].y), f2tf(pa[i].z), f2tf(pa[i].w)); \
            int brw = f4 >> 5, bc4 = (f4 & 31) * 4;                             \
            *(uint4*)&Bs[brw][bc4] =                                            \
                make_uint4(f2tf(pb[i].x), f2tf(pb[i].y), f2tf(pb[i].z), f2tf(pb[i].w)); \
        }                                                                       \
        __syncthreads();                                                        \
        if (k0c + 32 < Kdim) {                                                  \
            _Pragma("unroll")                                                   \
            for (int i = 0; i < 4; i++) {                                       \
                int f4 = tid + i * 256;                                         \
                int rw = f4 >> 3, c4 = (f4 & 7) * 4;                            \
                pa[i] = *(const float4*)&Aptr[(size_t)(row0 + rw) * Kdim + k0c + 32 + c4]; \
                int brw = f4 >> 5, bc4 = (f4 & 31) * 4;                         \
                pb[i] = *(const float4*)&Bptr[(size_t)(k0c + 32 + brw) * Ndim + col0 + bc4]; \
            }                                                                   \
        }                                                                       \
        _Pragma("unroll")                                                       \
        for (int k0 = 0; k0 < 32; k0 += 8) {                                    \
            uint32_t a[2][4], b2[8][2];                                         \
            _Pragma("unroll")                                                   \
            for (int mt = 0; mt < 2; mt++) {                                    \
                int r = wm + mt * 16 + g;                                       \
                a[mt][0] = As[r][k0 + t];     a[mt][1] = As[r + 8][k0 + t];     \
                a[mt][2] = As[r][k0 + t + 4]; a[mt][3] = As[r + 8][k0 + t + 4]; \
            }                                                                   \
            _Pragma("unroll")                                                   \
            for (int nt = 0; nt < 8; nt++) {                                    \
                int cn = wn + nt * 8 + g;                                       \
                b2[nt][0] = Bs[k0 + t][cn];                                     \
                b2[nt][1] = Bs[k0 + t + 4][cn];                                 \
            }                                                                   \
            _Pragma("unroll")                                                   \
            for (int mt = 0; mt < 2; mt++)                                      \
                _Pragma("unroll")                                               \
                for (int nt = 0; nt < 8; nt++) mma8(c[mt][nt], a[mt], b2[nt]);  \
        }                                                                       \
        __syncthreads();                                                        \
    }                                                                           \
    __VA_ARGS__

// ---------------- GEMM 1: heads = w @ qkv_w -> Qb/K/V (TF32) -----------------
__global__ __launch_bounds__(256)
void gemm_qkv_kernel(const float* __restrict__ A, const float* __restrict__ B,
                     const float* __restrict__ rbias) {
    NN_TF32_BODY(A, B, 1024, 3072, {
        for (int mt = 0; mt < 2; mt++) {
            for (int rr = 0; rr < 2; rr++) {
                int m = row0 + wm + mt * 16 + g + rr * 8;
                int q = m >> 1;
                int bb = m & 1;
                for (int nt = 0; nt < 8; nt++) {
                    int cc = col0 + wn + nt * 8 + 2 * t;
                    int sec = cc >> 10;
                    int h = (cc & 1023) >> 6;
                    int d = cc & 63;
                    size_t off = ((size_t)(bb * NH + h) * QLEN + q) * DH + d;
                    float vx = c[mt][nt][rr * 2 + 0];
                    float vy = c[mt][nt][rr * 2 + 1];
                    if (sec == 0) {
                        float2 rb = *(const float2*)&rbias[h * 64 + d];
                        float2 v;
                        v.x = vx + rb.x;
                        v.y = vy + rb.y;
                        *(float2*)&g_Qb[off] = v;
                    } else if (sec == 1) {
                        float2 v; v.x = vx; v.y = vy;
                        *(float2*)&g_K[off] = v;
                    } else {
                        float2 v; v.x = vx; v.y = vy;
                        *(float2*)&g_V[off] = v;
                    }
                }
            }
        }
    })
}

// ---------------- GEMM 2: r_head_k = r @ r_net_w -> Rk (TF32) ----------------
__global__ __launch_bounds__(256)
void gemm_rnet_kernel(const float* __restrict__ A, const float* __restrict__ B) {
    NN_TF32_BODY(A, B, 1024, 1024, {
        for (int mt = 0; mt < 2; mt++) {
            for (int rr = 0; rr < 2; rr++) {
                int m = row0 + wm + mt * 16 + g + rr * 8;
                for (int nt = 0; nt < 8; nt++) {
                    int cc = col0 + wn + nt * 8 + 2 * t;
                    int h = cc >> 6;
                    int d = cc & 63;
                    float2 v;
                    v.x = c[mt][nt][rr * 2 + 0];
                    v.y = c[mt][nt][rr * 2 + 1];
                    *(float2*)&g_Rk[((size_t)h * RLEN + m) * DH + d] = v;
                }
            }
        }
    })
}

// ---------------- GEMM 6: output = attn_vec @ o_w (TF32) ---------------------
__global__ __launch_bounds__(256)
void gemm_out_kernel(const float* __restrict__ B, float* __restrict__ out) {
    const float* A = g_AV;
    NN_TF32_BODY(A, B, 1024, 1024, {
        for (int mt = 0; mt < 2; mt++) {
            for (int rr = 0; rr < 2; rr++) {
                int m = row0 + wm + mt * 16 + g + rr * 8;
                for (int nt = 0; nt < 8; nt++) {
                    int cc = col0 + wn + nt * 8 + 2 * t;
                    float2 v;
                    v.x = c[mt][nt][rr * 2 + 0];
                    v.y = c[mt][nt][rr * 2 + 1];
                    *(float2*)&out[(size_t)m * 1024 + cc] = v;
                }
            }
        }
    })
}

// =============================================================================
// Fused score kernel (EXACT round-11 validated code): 512 threads / 16 warps,
// warp tile 32x32, scalar LDS fragments, Q reload for band qoff.
// SMEM: BDs[128][260] floats | Qs[128][68] | Ks[128][68] (tf32 words)
// =============================================================================
#define SMEM_STRIDE 68
#define BD_STRIDE 260
#define BD_WORDS (128 * BD_STRIDE)

__global__ __launch_bounds__(512, 1)
void score_fused_kernel(float* __restrict__ cov) {
    extern __shared__ uint32_t sm[];
    float* BDs = (float*)sm;                                   // 128 x 260 floats
    uint32_t (*Qs)[SMEM_STRIDE] = (uint32_t(*)[SMEM_STRIDE])(sm + BD_WORDS);
    uint32_t (*Ks)[SMEM_STRIDE] = (uint32_t(*)[SMEM_STRIDE])(sm + BD_WORDS + 128 * SMEM_STRIDE);

    int z = blockIdx.z;
    int b = z >> 4;
    int n = z & (NH - 1);
    const float* Qp  = g_Qb + (size_t)z * QLEN * DH;
    const float* Kp  = g_K  + (size_t)z * KLEN * DH;
    const float* Rkn = g_Rk + (size_t)n * RLEN * DH;
    int row0 = blockIdx.y * 128, col0 = blockIdx.x * 128;
    int tid = threadIdx.x;
    int wid = tid >> 5, lane = tid & 31, g = lane >> 2, t = lane & 3;
    int wm = (wid & 3) * 32, wn = (wid >> 2) * 32;   // 4x4 warp grid, 32x32 tiles

    // ---- phase 1: load Q, K; AC MMA ----
#pragma unroll
    for (int i = 0; i < 4; i++) {
        int f4 = tid + i * 512;
        int rw = f4 >> 4, c4 = (f4 & 15) * 4;
        float4 qa = *(const float4*)&Qp[(size_t)(row0 + rw) * DH + c4];
        float4 kb = *(const float4*)&Kp[(size_t)(col0 + rw) * DH + c4];
        *(uint4*)&Qs[rw][c4] = make_uint4(f2tf(qa.x), f2tf(qa.y), f2tf(qa.z), f2tf(qa.w));
        *(uint4*)&Ks[rw][c4] = make_uint4(f2tf(kb.x), f2tf(kb.y), f2tf(kb.z), f2tf(kb.w));
    }
    __syncthreads();
    float c[2][4][4] = {};
#pragma unroll
    for (int k0 = 0; k0 < 64; k0 += 8) {
        uint32_t a[2][4], b2[4][2];
#pragma unroll
        for (int mt = 0; mt < 2; mt++) {
            int r = wm + mt * 16 + g;
            a[mt][0] = Qs[r][k0 + t];     a[mt][1] = Qs[r + 8][k0 + t];
            a[mt][2] = Qs[r][k0 + t + 4]; a[mt][3] = Qs[r + 8][k0 + t + 4];
        }
#pragma unroll
        for (int nt = 0; nt < 4; nt++) {
            int r = wn + nt * 8 + g;
            b2[nt][0] = Ks[r][k0 + t];
            b2[nt][1] = Ks[r][k0 + t + 4];
        }
#pragma unroll
        for (int mt = 0; mt < 2; mt++)
#pragma unroll
            for (int nt = 0; nt < 4; nt++) mma8(c[mt][nt], a[mt], b2[nt]);
    }
    __syncthreads();   // AC done; Qs/Ks reusable

    // ---- band parameters (validated round 10) ----
    int below = (col0 < row0);
    int diag  = (col0 == row0);
    int d0 = col0 - row0;
    int qoffA   = (below || diag) ? 0 : 1;
    int rstartA = (below || diag) ? (1920 + d0) : (d0 - 129);
    int qoffB   = below ? 0 : 1;
    int rstartB = below ? (1920 + d0 + 128) : (diag ? -1 : (d0 - 129 + 128));

    int curQoff = 0;
#pragma unroll 1
    for (int half = 0; half < 2; half++) {
        int qoff   = half ? qoffB : qoffA;
        int rstart = half ? rstartB : rstartA;
        if (qoff != curQoff) {
#pragma unroll
            for (int i = 0; i < 4; i++) {
                int f4 = tid + i * 512;
                int rw = f4 >> 4, c4 = (f4 & 15) * 4;
                int qr = row0 + rw + qoff; if (qr > 2047) qr = 2047;
                float4 qa = *(const float4*)&Qp[(size_t)qr * DH + c4];
                *(uint4*)&Qs[rw][c4] = make_uint4(f2tf(qa.x), f2tf(qa.y), f2tf(qa.z), f2tf(qa.w));
            }
            curQoff = qoff;
        }
#pragma unroll
        for (int i = 0; i < 4; i++) {
            int f4 = tid + i * 512;
            int rw = f4 >> 4, c4 = (f4 & 15) * 4;
            int rr_ = rstart + rw; if (rr_ < 0) rr_ = 0; if (rr_ > 2047) rr_ = 2047;
            float4 kb = *(const float4*)&Rkn[(size_t)rr_ * DH + c4];
            *(uint4*)&Ks[rw][c4] = make_uint4(f2tf(kb.x), f2tf(kb.y), f2tf(kb.z), f2tf(kb.w));
        }
        __syncthreads();
        float c2[2][4][4] = {};
#pragma unroll
        for (int k0 = 0; k0 < 64; k0 += 8) {
            uint32_t a[2][4], b2[4][2];
#pragma unroll
            for (int mt = 0; mt < 2; mt++) {
                int r = wm + mt * 16 + g;
                a[mt][0] = Qs[r][k0 + t];     a[mt][1] = Qs[r + 8][k0 + t];
                a[mt][2] = Qs[r][k0 + t + 4]; a[mt][3] = Qs[r + 8][k0 + t + 4];
            }
#pragma unroll
            for (int nt = 0; nt < 4; nt++) {
                int r = wn + nt * 8 + g;
                b2[nt][0] = Ks[r][k0 + t];
                b2[nt][1] = Ks[r][k0 + t + 4];
            }
#pragma unroll
            for (int mt = 0; mt < 2; mt++)
#pragma unroll
                for (int nt = 0; nt < 4; nt++) mma8(c2[mt][nt], a[mt], b2[nt]);
        }
        // stage raw half into BDs columns [half*128, half*128+128)
#pragma unroll
        for (int mt = 0; mt < 2; mt++)
#pragma unroll
            for (int nt = 0; nt < 4; nt++)
#pragma unroll
                for (int rr = 0; rr < 2; rr++) {
                    int r = wm + mt * 16 + g + rr * 8;
                    int ccol = half * 128 + wn + nt * 8 + 2 * t;
                    float2 v;
                    v.x = c2[mt][nt][rr * 2 + 0];
                    v.y = c2[mt][nt][rr * 2 + 1];
                    *(float2*)&BDs[r * BD_STRIDE + ccol] = v;
                }
        __syncthreads();
    }

    // ---- epilogue: s = (AC + BDs[qi][127+ki-qi]) * scale + negmask ----
    const float* neg = g_negmask + (size_t)b * KLEN;
    float* Cz = cov + (size_t)z * QLEN * KLEN;
#pragma unroll
    for (int mt = 0; mt < 2; mt++) {
        int qi0 = wm + mt * 16 + g;
#pragma unroll
        for (int nt = 0; nt < 4; nt++) {
            int kloc = wn + nt * 8 + 2 * t;
            int kb = col0 + kloc;
            float2 ng = *(const float2*)&neg[kb];
#pragma unroll
            for (int rr = 0; rr < 2; rr++) {
                int qi = qi0 + rr * 8;
                int q = row0 + qi;
                int jj = 127 + kloc - qi;
                float bdx = (kb     == q + 1) ? 0.0f : BDs[qi * BD_STRIDE + jj];
                float bdy = (kb + 1 == q + 1) ? 0.0f : BDs[qi * BD_STRIDE + jj + 1];
                float2 s;
                s.x = (c[mt][nt][rr * 2 + 0] + bdx) * SCALE_L2E + ng.x;
                s.y = (c[mt][nt][rr * 2 + 1] + bdy) * SCALE_L2E + ng.y;
                *(float2*)&Cz[(size_t)q * KLEN + kb] = s;
            }
        }
    }
}

// ---------------- softmax over k (validated; base-2 domain) ------------------
__global__ __launch_bounds__(256)
void softmax_kernel(float* __restrict__ cov) {
    size_t row = blockIdx.x;
    float* p = cov + row * KLEN;
    int t = threadIdx.x;
    float4 v0 = ((const float4*)p)[t];
    float4 v1 = ((const float4*)p)[t + 256];
    float m = fmaxf(fmaxf(fmaxf(v0.x, v0.y), fmaxf(v0.z, v0.w)),
                    fmaxf(fmaxf(v1.x, v1.y), fmaxf(v1.z, v1.w)));
    __shared__ float sred[8];
#pragma unroll
    for (int o = 16; o; o >>= 1) m = fmaxf(m, __shfl_xor_sync(0xffffffffu, m, o));
    if ((t & 31) == 0) sred[t >> 5] = m;
    __syncthreads();
    if (t < 8) {
        float x = sred[t];
#pragma unroll
        for (int o = 4; o; o >>= 1) x = fmaxf(x, __shfl_xor_sync(0xffu, x, o));
        if (t == 0) sred[0] = x;
    }
    __syncthreads();
    m = sred[0];
    if (m == -INFINITY) {   // fully-masked row -> 0 per reference
        float4 zz = make_float4(0.f, 0.f, 0.f, 0.f);
        ((float4*)p)[t] = zz;
        ((float4*)p)[t + 256] = zz;
        return;
    }
    float e0x = fexp2(v0.x - m), e0y = fexp2(v0.y - m);
    float e0z = fexp2(v0.z - m), e0w = fexp2(v0.w - m);
    float e1x = fexp2(v1.x - m), e1y = fexp2(v1.y - m);
    float e1z = fexp2(v1.z - m), e1w = fexp2(v1.w - m);
    float s = (e0x + e0y) + (e0z + e0w) + (e1x + e1y) + (e1z + e1w);
    __shared__ float ssum[8];
#pragma unroll
    for (int o = 16; o; o >>= 1) s += __shfl_xor_sync(0xffffffffu, s, o);
    if ((t & 31) == 0) ssum[t >> 5] = s;
    __syncthreads();
    if (t < 8) {
        float x = ssum[t];
#pragma unroll
        for (int o = 4; o; o >>= 1) x += __shfl_xor_sync(0xffu, x, o);
        if (t == 0) ssum[0] = x;
    }
    __syncthreads();
    float inv = 1.0f / ssum[0];
    ((float4*)p)[t]       = make_float4(e0x * inv, e0y * inv, e0z * inv, e0w * inv);
    ((float4*)p)[t + 256] = make_float4(e1x * inv, e1y * inv, e1z * inv, e1w * inv);
}

// ---------------- PV: attn_vec = P @ V (TF32 MMA, 64-row tiles) --------------
// grid (32, 32): 1024 CTAs, 256 thr, warp grid 2x4 (warp tile 32x16),
// SMEM 34.8KB -> 3 CTAs/SM.
__global__ __launch_bounds__(256)
void pv_mma_kernel(const float* __restrict__ cov) {
    extern __shared__ uint32_t sm[];
    uint32_t (*Ps)[SMEM_STRIDE] = (uint32_t(*)[SMEM_STRIDE])sm;
    uint32_t (*Vs)[SMEM_STRIDE] = (uint32_t(*)[SMEM_STRIDE])(sm + 64 * SMEM_STRIDE);
    int z = blockIdx.y;
    int b = z >> 4, n = z & (NH - 1);
    const float* P = cov + (size_t)z * QLEN * KLEN;
    const float* Vm = g_V + (size_t)z * KLEN * DH;
    int row0 = blockIdx.x * 64;
    int tid = threadIdx.x;
    int wid = tid >> 5, lane = tid & 31, g = lane >> 2, t = lane & 3;
    int wm = (wid & 1) * 32, wn = (wid >> 1) * 16;
    float c[2][2][4] = {};
    for (int kc = 0; kc < KLEN; kc += 64) {
#pragma unroll
        for (int i = 0; i < 4; i++) {
            int f4 = tid + i * 256;
            int rw = f4 >> 4, c4 = (f4 & 15) * 4;
            float4 v = *(const float4*)&P[(size_t)(row0 + rw) * KLEN + kc + c4];
            *(uint4*)&Ps[rw][c4] = make_uint4(f2tf(v.x), f2tf(v.y), f2tf(v.z), f2tf(v.w));
        }
#pragma unroll
        for (int i = 0; i < 4; i++) {
            int f4 = tid + i * 256;
            int rw = f4 >> 4, c4 = (f4 & 15) * 4;
            float4 v = *(const float4*)&Vm[(size_t)(kc + rw) * DH + c4];
            *(uint4*)&Vs[rw][c4] = make_uint4(f2tf(v.x), f2tf(v.y), f2tf(v.z), f2tf(v.w));
        }
        __syncthreads();
#pragma unroll
        for (int k0 = 0; k0 < 64; k0 += 8) {
            uint32_t a[2][4], b2[2][2];
#pragma unroll
            for (int mt = 0; mt < 2; mt++) {
                int r = wm + mt * 16 + g;
                a[mt][0] = Ps[r][k0 + t];     a[mt][1] = Ps[r + 8][k0 + t];
                a[mt][2] = Ps[r][k0 + t + 4]; a[mt][3] = Ps[r + 8][k0 + t + 4];
            }
#pragma unroll
            for (int nt = 0; nt < 2; nt++) {
                int cn = wn + nt * 8 + g;
                b2[nt][0] = Vs[k0 + t][cn];
                b2[nt][1] = Vs[k0 + t + 4][cn];
            }
#pragma unroll
            for (int mt = 0; mt < 2; mt++)
#pragma unroll
                for (int nt = 0; nt < 2; nt++) mma8(c[mt][nt], a[mt], b2[nt]);
        }
        __syncthreads();
    }
#pragma unroll
    for (int mt = 0; mt < 2; mt++) {
        int q0 = row0 + wm + mt * 16 + g;
#pragma unroll
        for (int nt = 0; nt < 2; nt++) {
            int d = wn + nt * 8 + 2 * t;
#pragma unroll
            for (int rr = 0; rr < 2; rr++) {
                int q = q0 + rr * 8;
                float2 v;
                v.x = c[mt][nt][rr * 2 + 0];
                v.y = c[mt][nt][rr * 2 + 1];
                *(float2*)&g_AV[((size_t)q * BSZ + b) * DM + n * DH + d] = v;
            }
        }
    }
}

// ---------------- launch ------------------------------------------------------
extern "C" void kernel_launch(void* const* d_in, const int* in_sizes, int n_in,
                              void* d_out, int out_size) {
    const float* w       = (const float*)d_in[0];
    const float* r       = (const float*)d_in[1];
    const void*  mask    = d_in[2];
    const float* qkv_w   = (const float*)d_in[3];
    const float* r_net_w = (const float*)d_in[4];
    const float* o_w     = (const float*)d_in[5];
    const float* r_r_bias = (const float*)d_in[7];  // reference bug: r_r_bias for both

    float* out = (float*)d_out;
    float* cov = out + (size_t)QLEN * BSZ * DM;

    const int SMEM_FUSED = (BD_WORDS + 2 * 128 * SMEM_STRIDE) * 4;  // 202752
    const int SMEM_PV    = (64 + 64) * SMEM_STRIDE * 4;             // 34816
    static int attr_done = 0;
    if (!attr_done) {
        cudaFuncSetAttribute(score_fused_kernel, cudaFuncAttributeMaxDynamicSharedMemorySize, SMEM_FUSED);
        cudaFuncSetAttribute(pv_mma_kernel,      cudaFuncAttributeMaxDynamicSharedMemorySize, SMEM_PV);
        attr_done = 1;
    }

    mask_expand_kernel<<<1, 256>>>((const unsigned char*)mask);
    gemm_qkv_kernel<<<dim3(24, 32), 256>>>(w, qkv_w, r_r_bias);
    gemm_rnet_kernel<<<dim3(8, 16), 256>>>(r, r_net_w);
    score_fused_kernel<<<dim3(16, 16, BSZ * NH), 512, SMEM_FUSED>>>(cov);
    softmax_kernel<<<BSZ * NH * QLEN, 256>>>(cov);
    pv_mma_kernel<<<dim3(32, BSZ * NH), 256, SMEM_PV>>>(cov);
    gemm_out_kernel<<<dim3(8, 32), 256>>>(o_w, out);
}

// round 16
// speedup vs baseline: 1.5327x; 1.0306x over previous
#include <cuda_runtime.h>
#include <cuda_bf16.h>
#include <math.h>
#include <stdint.h>

#define QLEN  2048
#define BSZ   2
#define NH    16
#define DH    64
#define DM    1024
#define KLEN  2048
#define RLEN  2048
// 0.125 * log2(e): scores stored in base-2 domain so softmax uses 2^x
#define SCALE_L2E 0.1803368801111244f

// ---------------- scratch (device globals) ----------------------------------
__device__ float g_Qb[(size_t)BSZ * NH * QLEN * DH];   // Q + r_r_bias, (b,n,q,d)
__device__ float g_K [(size_t)BSZ * NH * KLEN * DH];   // (b,n,k,d)
__device__ float g_V [(size_t)BSZ * NH * KLEN * DH];   // (b,n,k,d)
__device__ float g_Rk[(size_t)NH * RLEN * DH];         // (n,r,d)
__device__ float g_AV[(size_t)QLEN * BSZ * DM];        // attn_vec (q,b,n*d)
__device__ float g_negmask[(size_t)BSZ * KLEN];        // 0 or -inf, [b][k]

// ---------------- helpers -----------------------------------------------------
__device__ __forceinline__ uint32_t f2tf(float f) {
    uint32_t u; asm("cvt.rna.tf32.f32 %0, %1;" : "=r"(u) : "f"(f)); return u;
}
__device__ __forceinline__ void mma8(float* c, const uint32_t* a, const uint32_t* b) {
    asm volatile(
        "mma.sync.aligned.m16n8k8.row.col.f32.tf32.tf32.f32 "
        "{%0,%1,%2,%3}, {%4,%5,%6,%7}, {%8,%9}, {%0,%1,%2,%3};"
        : "+f"(c[0]), "+f"(c[1]), "+f"(c[2]), "+f"(c[3])
        : "r"(a[0]), "r"(a[1]), "r"(a[2]), "r"(a[3]), "r"(b[0]), "r"(b[1]));
}
// branch-free 2^t on FMA/ALU pipes. t <= 0 expected; -inf -> ~0.
__device__ __forceinline__ float fexp2(float t) {
    t = fmaxf(t, -126.0f);
    float u = t + 12582912.0f;
    int ki = __float_as_int(u) - 0x4B400000;
    float fk = u - 12582912.0f;
    float f = t - fk;
    float p = 0.0013333558f;
    p = fmaf(p, f, 0.0096181291f);
    p = fmaf(p, f, 0.0555041087f);
    p = fmaf(p, f, 0.2402265069f);
    p = fmaf(p, f, 0.6931471806f);
    p = fmaf(p, f, 1.0f);
    return __int_as_float(__float_as_int(p) + (ki << 23));
}

// ---------------- mask detect + expand (validated) ---------------------------
__global__ void mask_expand_kernel(const unsigned char* __restrict__ m) {
    __shared__ int cnt[4];
    __shared__ int smode;
    if (threadIdx.x < 4) cnt[threadIdx.x] = 0;
    __syncthreads();
    for (int i = threadIdx.x; i < 4096; i += blockDim.x)
        if (m[i]) atomicAdd(&cnt[i & 3], 1);
    __syncthreads();
    if (threadIdx.x == 0) {
        int mode;
        if (cnt[1] == 0 && cnt[2] == 0 && cnt[3] == 0) mode = 0;      // int32
        else if (cnt[0] == 0 && cnt[1] == 0)           mode = 1;      // float32
        else                                           mode = 2;      // bool byte
        smode = mode;
    }
    __syncthreads();
    int mode = smode;
    for (int idx = threadIdx.x; idx < KLEN * BSZ; idx += blockDim.x) {
        bool msk;
        if (mode == 0)      msk = ((const int*)m)[idx] != 0;
        else if (mode == 1) msk = ((const float*)m)[idx] != 0.0f;
        else                msk = m[idx] != 0;
        int k = idx >> 1, b = idx & 1;
        g_negmask[b * KLEN + k] = msk ? -INFINITY : 0.0f;
    }
}

// =============================================================================
// NN TF32 MMA GEMM body (validated round 6)
// =============================================================================
#define NN_TF32_BODY(Aptr, Bptr, Kdim, Ndim, ...)                               \
    __shared__ uint32_t As[128][36];                                            \
    __shared__ uint32_t Bs[32][136];                                            \
    int tid = threadIdx.x;                                                      \
    int row0 = blockIdx.y * 128, col0 = blockIdx.x * 128;                       \
    int wid = tid >> 5, lane = tid & 31, g = lane >> 2, t = lane & 3;           \
    int wm = (wid & 3) * 32, wn = (wid >> 2) * 64;                              \
    (void)lane;                                                                 \
    float c[2][8][4] = {};                                                      \
    float4 pa[4], pb[4];                                                        \
    _Pragma("unroll")                                                           \
    for (int i = 0; i < 4; i++) {                                               \
        int f4 = tid + i * 256;                                                 \
        int rw = f4 >> 3, c4 = (f4 & 7) * 4;                                    \
        pa[i] = *(const float4*)&Aptr[(size_t)(row0 + rw) * Kdim + c4];         \
        int brw = f4 >> 5, bc4 = (f4 & 31) * 4;                                 \
        pb[i] = *(const float4*)&Bptr[(size_t)brw * Ndim + col0 + bc4];         \
    }                                                                           \
    for (int k0c = 0; k0c < Kdim; k0c += 32) {                                  \
        _Pragma("unroll")                                                       \
        for (int i = 0; i < 4; i++) {                                           \
            int f4 = tid + i * 256;                                             \
            int rw = f4 >> 3, c4 = (f4 & 7) * 4;                                \
            *(uint4*)&As[rw][c4] =                                              \
                make_uint4(f2tf(pa[i].x), f2tf(pa[i].y), f2tf(pa[i].z), f2tf(pa[i].w)); \
            int brw = f4 >> 5, bc4 = (f4 & 31) * 4;                             \
            *(uint4*)&Bs[brw][bc4] =                                            \
                make_uint4(f2tf(pb[i].x), f2tf(pb[i].y), f2tf(pb[i].z), f2tf(pb[i].w)); \
        }                                                                       \
        __syncthreads();                                                        \
        if (k0c + 32 < Kdim) {                                                  \
            _Pragma("unroll")                                                   \
            for (int i = 0; i < 4; i++) {                                       \
                int f4 = tid + i * 256;                                         \
                int rw = f4 >> 3, c4 = (f4 & 7) * 4;                            \
                pa[i] = *(const float4*)&Aptr[(size_t)(row0 + rw) * Kdim + k0c + 32 + c4]; \
                int brw = f4 >> 5, bc4 = (f4 & 31) * 4;                         \
                pb[i] = *(const float4*)&Bptr[(size_t)(k0c + 32 + brw) * Ndim + col0 + bc4]; \
            }                                                                   \
        }                                                                       \
        _Pragma("unroll")                                                       \
        for (int k0 = 0; k0 < 32; k0 += 8) {                                    \
            uint32_t a[2][4], b2[8][2];                                         \
            _Pragma("unroll")                                                   \
            for (int mt = 0; mt < 2; mt++) {                                    \
                int r = wm + mt * 16 + g;                                       \
                a[mt][0] = As[r][k0 + t];     a[mt][1] = As[r + 8][k0 + t];     \
                a[mt][2] = As[r][k0 + t + 4]; a[mt][3] = As[r + 8][k0 + t + 4]; \
            }                                                                   \
            _Pragma("unroll")                                                   \
            for (int nt = 0; nt < 8; nt++) {                                    \
                int cn = wn + nt * 8 + g;                                       \
                b2[nt][0] = Bs[k0 + t][cn];                                     \
                b2[nt][1] = Bs[k0 + t + 4][cn];                                 \
            }                                                                   \
            _Pragma("unroll")                                                   \
            for (int mt = 0; mt < 2; mt++)                                      \
                _Pragma("unroll")                                               \
                for (int nt = 0; nt < 8; nt++) mma8(c[mt][nt], a[mt], b2[nt]);  \
        }                                                                       \
        __syncthreads();                                                        \
    }                                                                           \
    __VA_ARGS__

// ---------------- GEMM 1: heads = w @ qkv_w -> Qb/K/V (TF32) -----------------
__global__ __launch_bounds__(256)
void gemm_qkv_kernel(const float* __restrict__ A, const float* __restrict__ B,
                     const float* __restrict__ rbias) {
    NN_TF32_BODY(A, B, 1024, 3072, {
        for (int mt = 0; mt < 2; mt++) {
            for (int rr = 0; rr < 2; rr++) {
                int m = row0 + wm + mt * 16 + g + rr * 8;
                int q = m >> 1;
                int bb = m & 1;
                for (int nt = 0; nt < 8; nt++) {
                    int cc = col0 + wn + nt * 8 + 2 * t;
                    int sec = cc >> 10;
                    int h = (cc & 1023) >> 6;
                    int d = cc & 63;
                    size_t off = ((size_t)(bb * NH + h) * QLEN + q) * DH + d;
                    float vx = c[mt][nt][rr * 2 + 0];
                    float vy = c[mt][nt][rr * 2 + 1];
                    if (sec == 0) {
                        float2 rb = *(const float2*)&rbias[h * 64 + d];
                        float2 v;
                        v.x = vx + rb.x;
                        v.y = vy + rb.y;
                        *(float2*)&g_Qb[off] = v;
                    } else if (sec == 1) {
                        float2 v; v.x = vx; v.y = vy;
                        *(float2*)&g_K[off] = v;
                    } else {
                        float2 v; v.x = vx; v.y = vy;
                        *(float2*)&g_V[off] = v;
                    }
                }
            }
        }
    })
}

// ---------------- GEMM 2: r_head_k = r @ r_net_w -> Rk (TF32) ----------------
__global__ __launch_bounds__(256)
void gemm_rnet_kernel(const float* __restrict__ A, const float* __restrict__ B) {
    NN_TF32_BODY(A, B, 1024, 1024, {
        for (int mt = 0; mt < 2; mt++) {
            for (int rr = 0; rr < 2; rr++) {
                int m = row0 + wm + mt * 16 + g + rr * 8;
                for (int nt = 0; nt < 8; nt++) {
                    int cc = col0 + wn + nt * 8 + 2 * t;
                    int h = cc >> 6;
                    int d = cc & 63;
                    float2 v;
                    v.x = c[mt][nt][rr * 2 + 0];
                    v.y = c[mt][nt][rr * 2 + 1];
                    *(float2*)&g_Rk[((size_t)h * RLEN + m) * DH + d] = v;
                }
            }
        }
    })
}

// ---------------- GEMM 6: output = attn_vec @ o_w (TF32) ---------------------
__global__ __launch_bounds__(256)
void gemm_out_kernel(const float* __restrict__ B, float* __restrict__ out) {
    const float* A = g_AV;
    NN_TF32_BODY(A, B, 1024, 1024, {
        for (int mt = 0; mt < 2; mt++) {
            for (int rr = 0; rr < 2; rr++) {
                int m = row0 + wm + mt * 16 + g + rr * 8;
                for (int nt = 0; nt < 8; nt++) {
                    int cc = col0 + wn + nt * 8 + 2 * t;
                    float2 v;
                    v.x = c[mt][nt][rr * 2 + 0];
                    v.y = c[mt][nt][rr * 2 + 1];
                    *(float2*)&out[(size_t)m * 1024 + cc] = v;
                }
            }
        }
    })
}

// =============================================================================
// Fused score kernel: 64x128 output tiles, 256 threads / 8 warps, 2 CTAs/SM.
// Band staged in three 64-wide segments (jj in [64,256)); jj<64 never read.
//   main band:  raw(q,   1920+d0 + jj)   (valid while jj <= 127-d0)
//   leak band:  raw(q+1, d0-129  + jj)
//   segment s main iff 64s+63 <= 127-d0 (boundary always at block edge;
//   off-by-one slot is k==q+1, zeroed in epilogue).
// SMEM: BDs[64][196] floats | Qs[65][68] | Ks[128][68] = 102,672 B
// =============================================================================
#define SMEM_STRIDE 68
#define BD_STRIDE2 196
#define BD_WORDS2 (64 * BD_STRIDE2)

__global__ __launch_bounds__(256, 2)
void score_fused_kernel(float* __restrict__ cov) {
    extern __shared__ uint32_t sm[];
    float* BDs = (float*)sm;                                   // 64 x 196 floats
    uint32_t (*Qs)[SMEM_STRIDE] = (uint32_t(*)[SMEM_STRIDE])(sm + BD_WORDS2);          // 65 rows
    uint32_t (*Ks)[SMEM_STRIDE] = (uint32_t(*)[SMEM_STRIDE])(sm + BD_WORDS2 + 65 * SMEM_STRIDE);

    int z = blockIdx.z;
    int b = z >> 4;
    int n = z & (NH - 1);
    const float* Qp  = g_Qb + (size_t)z * QLEN * DH;
    const float* Kp  = g_K  + (size_t)z * KLEN * DH;
    const float* Rkn = g_Rk + (size_t)n * RLEN * DH;
    int row0 = blockIdx.y * 64, col0 = blockIdx.x * 128;
    int tid = threadIdx.x;
    int wid = tid >> 5, lane = tid & 31, g = lane >> 2, t = lane & 3;
    int wm = (wid & 1) * 32, wn = (wid >> 1) * 32;   // AC: 2x4 warp grid, 32x32 tiles

    // ---- load Q rows row0..row0+64 (65 rows; last clamped, read only in-range)
#pragma unroll
    for (int i = 0; i < 5; i++) {
        int f4 = tid + i * 256;
        if (f4 < 65 * 16) {
            int rw = f4 >> 4, c4 = (f4 & 15) * 4;
            int qr = row0 + rw; if (qr > 2047) qr = 2047;
            float4 qa = *(const float4*)&Qp[(size_t)qr * DH + c4];
            *(uint4*)&Qs[rw][c4] = make_uint4(f2tf(qa.x), f2tf(qa.y), f2tf(qa.z), f2tf(qa.w));
        }
    }
    // ---- load K tile (128 rows) ----
#pragma unroll
    for (int i = 0; i < 8; i++) {
        int f4 = tid + i * 256;
        int rw = f4 >> 4, c4 = (f4 & 15) * 4;
        float4 kb = *(const float4*)&Kp[(size_t)(col0 + rw) * DH + c4];
        *(uint4*)&Ks[rw][c4] = make_uint4(f2tf(kb.x), f2tf(kb.y), f2tf(kb.z), f2tf(kb.w));
    }
    __syncthreads();

    // ---- AC MMA ----
    float c[2][4][4] = {};
#pragma unroll
    for (int k0 = 0; k0 < 64; k0 += 8) {
        uint32_t a[2][4], b2[4][2];
#pragma unroll
        for (int mt = 0; mt < 2; mt++) {
            int r = wm + mt * 16 + g;
            a[mt][0] = Qs[r][k0 + t];     a[mt][1] = Qs[r + 8][k0 + t];
            a[mt][2] = Qs[r][k0 + t + 4]; a[mt][3] = Qs[r + 8][k0 + t + 4];
        }
#pragma unroll
        for (int nt = 0; nt < 4; nt++) {
            int r = wn + nt * 8 + g;
            b2[nt][0] = Ks[r][k0 + t];
            b2[nt][1] = Ks[r][k0 + t + 4];
        }
#pragma unroll
        for (int mt = 0; mt < 2; mt++)
#pragma unroll
            for (int nt = 0; nt < 4; nt++) mma8(c[mt][nt], a[mt], b2[nt]);
    }
    __syncthreads();   // AC done; Ks reusable

    // ---- band segments s = 1..3 (jj in [64s, 64s+64)) ----
    int d0 = col0 - row0;
    int bwn = (wid >> 1) * 16;           // band: 2x4 warp grid over 64x64, 32x16 tiles
#pragma unroll 1
    for (int s = 1; s <= 3; s++) {
        int mainb  = (64 * s + 63 <= 127 - d0);
        int qoff   = mainb ? 0 : 1;
        int rstart = (mainb ? (1920 + d0) : (d0 - 129)) + 64 * s;
        // load Rk segment rows (64, clamped) into Ks[0..64)
#pragma unroll
        for (int i = 0; i < 4; i++) {
            int f4 = tid + i * 256;
            int rw = f4 >> 4, c4 = (f4 & 15) * 4;
            int rr_ = rstart + rw; if (rr_ < 0) rr_ = 0; if (rr_ > 2047) rr_ = 2047;
            float4 kb = *(const float4*)&Rkn[(size_t)rr_ * DH + c4];
            *(uint4*)&Ks[rw][c4] = make_uint4(f2tf(kb.x), f2tf(kb.y), f2tf(kb.z), f2tf(kb.w));
        }
        __syncthreads();
        float c2[2][2][4] = {};
#pragma unroll
        for (int k0 = 0; k0 < 64; k0 += 8) {
            uint32_t a[2][4], b2[2][2];
#pragma unroll
            for (int mt = 0; mt < 2; mt++) {
                int r = wm + mt * 16 + qoff + g;
                a[mt][0] = Qs[r][k0 + t];     a[mt][1] = Qs[r + 8][k0 + t];
                a[mt][2] = Qs[r][k0 + t + 4]; a[mt][3] = Qs[r + 8][k0 + t + 4];
            }
#pragma unroll
            for (int nt = 0; nt < 2; nt++) {
                int r = bwn + nt * 8 + g;
                b2[nt][0] = Ks[r][k0 + t];
                b2[nt][1] = Ks[r][k0 + t + 4];
            }
#pragma unroll
            for (int mt = 0; mt < 2; mt++)
#pragma unroll
                for (int nt = 0; nt < 2; nt++) mma8(c2[mt][nt], a[mt], b2[nt]);
        }
        // stage into BDs at jjo = 64*(s-1) + local col
#pragma unroll
        for (int mt = 0; mt < 2; mt++)
#pragma unroll
            for (int nt = 0; nt < 2; nt++)
#pragma unroll
                for (int rr = 0; rr < 2; rr++) {
                    int r = wm + mt * 16 + g + rr * 8;
                    int ccol = 64 * (s - 1) + bwn + nt * 8 + 2 * t;
                    float2 v;
                    v.x = c2[mt][nt][rr * 2 + 0];
                    v.y = c2[mt][nt][rr * 2 + 1];
                    *(float2*)&BDs[r * BD_STRIDE2 + ccol] = v;
                }
        __syncthreads();
    }

    // ---- epilogue: s = (AC + BDs[qi][63+kloc-qi]) * scale + negmask ----
    const float* neg = g_negmask + (size_t)b * KLEN;
    float* Cz = cov + (size_t)z * QLEN * KLEN;
#pragma unroll
    for (int mt = 0; mt < 2; mt++) {
        int qi0 = wm + mt * 16 + g;
#pragma unroll
        for (int nt = 0; nt < 4; nt++) {
            int kloc = wn + nt * 8 + 2 * t;
            int kb = col0 + kloc;
            float2 ng = *(const float2*)&neg[kb];
#pragma unroll
            for (int rr = 0; rr < 2; rr++) {
                int qi = qi0 + rr * 8;
                int q = row0 + qi;
                int jjo = 63 + kloc - qi;
                float bdx = (kb     == q + 1) ? 0.0f : BDs[qi * BD_STRIDE2 + jjo];
                float bdy = (kb + 1 == q + 1) ? 0.0f : BDs[qi * BD_STRIDE2 + jjo + 1];
                float2 s;
                s.x = (c[mt][nt][rr * 2 + 0] + bdx) * SCALE_L2E + ng.x;
                s.y = (c[mt][nt][rr * 2 + 1] + bdy) * SCALE_L2E + ng.y;
                *(float2*)&Cz[(size_t)q * KLEN + kb] = s;
            }
        }
    }
}

// ---------------- softmax over k (validated; base-2 domain) ------------------
__global__ __launch_bounds__(256)
void softmax_kernel(float* __restrict__ cov) {
    size_t row = blockIdx.x;
    float* p = cov + row * KLEN;
    int t = threadIdx.x;
    float4 v0 = ((const float4*)p)[t];
    float4 v1 = ((const float4*)p)[t + 256];
    float m = fmaxf(fmaxf(fmaxf(v0.x, v0.y), fmaxf(v0.z, v0.w)),
                    fmaxf(fmaxf(v1.x, v1.y), fmaxf(v1.z, v1.w)));
    __shared__ float sred[8];
#pragma unroll
    for (int o = 16; o; o >>= 1) m = fmaxf(m, __shfl_xor_sync(0xffffffffu, m, o));
    if ((t & 31) == 0) sred[t >> 5] = m;
    __syncthreads();
    if (t < 8) {
        float x = sred[t];
#pragma unroll
        for (int o = 4; o; o >>= 1) x = fmaxf(x, __shfl_xor_sync(0xffu, x, o));
        if (t == 0) sred[0] = x;
    }
    __syncthreads();
    m = sred[0];
    if (m == -INFINITY) {   // fully-masked row -> 0 per reference
        float4 zz = make_float4(0.f, 0.f, 0.f, 0.f);
        ((float4*)p)[t] = zz;
        ((float4*)p)[t + 256] = zz;
        return;
    }
    float e0x = fexp2(v0.x - m), e0y = fexp2(v0.y - m);
    float e0z = fexp2(v0.z - m), e0w = fexp2(v0.w - m);
    float e1x = fexp2(v1.x - m), e1y = fexp2(v1.y - m);
    float e1z = fexp2(v1.z - m), e1w = fexp2(v1.w - m);
    float s = (e0x + e0y) + (e0z + e0w) + (e1x + e1y) + (e1z + e1w);
    __shared__ float ssum[8];
#pragma unroll
    for (int o = 16; o; o >>= 1) s += __shfl_xor_sync(0xffffffffu, s, o);
    if ((t & 31) == 0) ssum[t >> 5] = s;
    __syncthreads();
    if (t < 8) {
        float x = ssum[t];
#pragma unroll
        for (int o = 4; o; o >>= 1) x += __shfl_xor_sync(0xffu, x, o);
        if (t == 0) ssum[0] = x;
    }
    __syncthreads();
    float inv = 1.0f / ssum[0];
    ((float4*)p)[t]       = make_float4(e0x * inv, e0y * inv, e0z * inv, e0w * inv);
    ((float4*)p)[t + 256] = make_float4(e1x * inv, e1y * inv, e1z * inv, e1w * inv);
}

// ---------------- PV: attn_vec = P @ V (TF32 MMA, 64-row tiles; validated r15)
__global__ __launch_bounds__(256)
void pv_mma_kernel(const float* __restrict__ cov) {
    extern __shared__ uint32_t sm[];
    uint32_t (*Ps)[SMEM_STRIDE] = (uint32_t(*)[SMEM_STRIDE])sm;
    uint32_t (*Vs)[SMEM_STRIDE] = (uint32_t(*)[SMEM_STRIDE])(sm + 64 * SMEM_STRIDE);
    int z = blockIdx.y;
    int b = z >> 4, n = z & (NH - 1);
    const float* P = cov + (size_t)z * QLEN * KLEN;
    const float* Vm = g_V + (size_t)z * KLEN * DH;
    int row0 = blockIdx.x * 64;
    int tid = threadIdx.x;
    int wid = tid >> 5, lane = tid & 31, g = lane >> 2, t = lane & 3;
    int wm = (wid & 1) * 32, wn = (wid >> 1) * 16;
    float c[2][2][4] = {};
    for (int kc = 0; kc < KLEN; kc += 64) {
#pragma unroll
        for (int i = 0; i < 4; i++) {
            int f4 = tid + i * 256;
            int rw = f4 >> 4, c4 = (f4 & 15) * 4;
            float4 v = *(const float4*)&P[(size_t)(row0 + rw) * KLEN + kc + c4];
            *(uint4*)&Ps[rw][c4] = make_uint4(f2tf(v.x), f2tf(v.y), f2tf(v.z), f2tf(v.w));
        }
#pragma unroll
        for (int i = 0; i < 4; i++) {
            int f4 = tid + i * 256;
            int rw = f4 >> 4, c4 = (f4 & 15) * 4;
            float4 v = *(const float4*)&Vm[(size_t)(kc + rw) * DH + c4];
            *(uint4*)&Vs[rw][c4] = make_uint4(f2tf(v.x), f2tf(v.y), f2tf(v.z), f2tf(v.w));
        }
        __syncthreads();
#pragma unroll
        for (int k0 = 0; k0 < 64; k0 += 8) {
            uint32_t a[2][4], b2[2][2];
#pragma unroll
            for (int mt = 0; mt < 2; mt++) {
                int r = wm + mt * 16 + g;
                a[mt][0] = Ps[r][k0 + t];     a[mt][1] = Ps[r + 8][k0 + t];
                a[mt][2] = Ps[r][k0 + t + 4]; a[mt][3] = Ps[r + 8][k0 + t + 4];
            }
#pragma unroll
            for (int nt = 0; nt < 2; nt++) {
                int cn = wn + nt * 8 + g;
                b2[nt][0] = Vs[k0 + t][cn];
                b2[nt][1] = Vs[k0 + t + 4][cn];
            }
#pragma unroll
            for (int mt = 0; mt < 2; mt++)
#pragma unroll
                for (int nt = 0; nt < 2; nt++) mma8(c[mt][nt], a[mt], b2[nt]);
        }
        __syncthreads();
    }
#pragma unroll
    for (int mt = 0; mt < 2; mt++) {
        int q0 = row0 + wm + mt * 16 + g;
#pragma unroll
        for (int nt = 0; nt < 2; nt++) {
            int d = wn + nt * 8 + 2 * t;
#pragma unroll
            for (int rr = 0; rr < 2; rr++) {
                int q = q0 + rr * 8;
                float2 v;
                v.x = c[mt][nt][rr * 2 + 0];
                v.y = c[mt][nt][rr * 2 + 1];
                *(float2*)&g_AV[((size_t)q * BSZ + b) * DM + n * DH + d] = v;
            }
        }
    }
}

// ---------------- launch ------------------------------------------------------
extern "C" void kernel_launch(void* const* d_in, const int* in_sizes, int n_in,
                              void* d_out, int out_size) {
    const float* w       = (const float*)d_in[0];
    const float* r       = (const float*)d_in[1];
    const void*  mask    = d_in[2];
    const float* qkv_w   = (const float*)d_in[3];
    const float* r_net_w = (const float*)d_in[4];
    const float* o_w     = (const float*)d_in[5];
    const float* r_r_bias = (const float*)d_in[7];  // reference bug: r_r_bias for both

    float* out = (float*)d_out;
    float* cov = out + (size_t)QLEN * BSZ * DM;

    const int SMEM_FUSED = (BD_WORDS2 + (65 + 128) * SMEM_STRIDE) * 4;  // 102672
    const int SMEM_PV    = (64 + 64) * SMEM_STRIDE * 4;                 // 34816
    static int attr_done = 0;
    if (!attr_done) {
        cudaFuncSetAttribute(score_fused_kernel, cudaFuncAttributeMaxDynamicSharedMemorySize, SMEM_FUSED);
        cudaFuncSetAttribute(pv_mma_kernel,      cudaFuncAttributeMaxDynamicSharedMemorySize, SMEM_PV);
        attr_done = 1;
    }

    mask_expand_kernel<<<1, 256>>>((const unsigned char*)mask);
    gemm_qkv_kernel<<<dim3(24, 32), 256>>>(w, qkv_w, r_r_bias);
    gemm_rnet_kernel<<<dim3(8, 16), 256>>>(r, r_net_w);
    score_fused_kernel<<<dim3(16, 32, BSZ * NH), 256, SMEM_FUSED>>>(cov);
    softmax_kernel<<<BSZ * NH * QLEN, 256>>>(cov);
    pv_mma_kernel<<<dim3(32, BSZ * NH), 256, SMEM_PV>>>(cov);
    gemm_out_kernel<<<dim3(8, 32), 256>>>(o_w, out);
}

// round 17
// speedup vs baseline: 1.5383x; 1.0036x over previous
#include <cuda_runtime.h>
#include <cuda_bf16.h>
#include <math.h>
#include <stdint.h>

#define QLEN  2048
#define BSZ   2
#define NH    16
#define DH    64
#define DM    1024
#define KLEN  2048
#define RLEN  2048
// 0.125 * log2(e): scores stored in base-2 domain so softmax uses 2^x
#define SCALE_L2E 0.1803368801111244f

// ---------------- scratch (device globals) ----------------------------------
__device__ float g_Qb[(size_t)BSZ * NH * QLEN * DH];   // Q + r_r_bias, (b,n,q,d)
__device__ float g_K [(size_t)BSZ * NH * KLEN * DH];   // (b,n,k,d)
__device__ float g_V [(size_t)BSZ * NH * KLEN * DH];   // (b,n,k,d)
__device__ float g_Rk[(size_t)NH * RLEN * DH];         // (n,r,d)
__device__ float g_AV[(size_t)QLEN * BSZ * DM];        // attn_vec (q,b,n*d)
__device__ float g_negmask[(size_t)BSZ * KLEN];        // 0 or -inf, [b][k]

// ---------------- helpers -----------------------------------------------------
__device__ __forceinline__ uint32_t f2tf(float f) {
    uint32_t u; asm("cvt.rna.tf32.f32 %0, %1;" : "=r"(u) : "f"(f)); return u;
}
__device__ __forceinline__ void mma8(float* c, const uint32_t* a, const uint32_t* b) {
    asm volatile(
        "mma.sync.aligned.m16n8k8.row.col.f32.tf32.tf32.f32 "
        "{%0,%1,%2,%3}, {%4,%5,%6,%7}, {%8,%9}, {%0,%1,%2,%3};"
        : "+f"(c[0]), "+f"(c[1]), "+f"(c[2]), "+f"(c[3])
        : "r"(a[0]), "r"(a[1]), "r"(a[2]), "r"(a[3]), "r"(b[0]), "r"(b[1]));
}
// branch-free 2^t on FMA/ALU pipes. t <= 0 expected; -inf -> ~0.
__device__ __forceinline__ float fexp2(float t) {
    t = fmaxf(t, -126.0f);
    float u = t + 12582912.0f;
    int ki = __float_as_int(u) - 0x4B400000;
    float fk = u - 12582912.0f;
    float f = t - fk;
    float p = 0.0013333558f;
    p = fmaf(p, f, 0.0096181291f);
    p = fmaf(p, f, 0.0555041087f);
    p = fmaf(p, f, 0.2402265069f);
    p = fmaf(p, f, 0.6931471806f);
    p = fmaf(p, f, 1.0f);
    return __int_as_float(__float_as_int(p) + (ki << 23));
}

// ---------------- mask detect + expand (validated) ---------------------------
__global__ void mask_expand_kernel(const unsigned char* __restrict__ m) {
    __shared__ int cnt[4];
    __shared__ int smode;
    if (threadIdx.x < 4) cnt[threadIdx.x] = 0;
    __syncthreads();
    for (int i = threadIdx.x; i < 4096; i += blockDim.x)
        if (m[i]) atomicAdd(&cnt[i & 3], 1);
    __syncthreads();
    if (threadIdx.x == 0) {
        int mode;
        if (cnt[1] == 0 && cnt[2] == 0 && cnt[3] == 0) mode = 0;      // int32
        else if (cnt[0] == 0 && cnt[1] == 0)           mode = 1;      // float32
        else                                           mode = 2;      // bool byte
        smode = mode;
    }
    __syncthreads();
    int mode = smode;
    for (int idx = threadIdx.x; idx < KLEN * BSZ; idx += blockDim.x) {
        bool msk;
        if (mode == 0)      msk = ((const int*)m)[idx] != 0;
        else if (mode == 1) msk = ((const float*)m)[idx] != 0.0f;
        else                msk = m[idx] != 0;
        int k = idx >> 1, b = idx & 1;
        g_negmask[b * KLEN + k] = msk ? -INFINITY : 0.0f;
    }
}

// =============================================================================
// NN TF32 MMA GEMM body (validated round 6)
// =============================================================================
#define NN_TF32_BODY(Aptr, Bptr, Kdim, Ndim, ...)                               \
    __shared__ uint32_t As[128][36];                                            \
    __shared__ uint32_t Bs[32][136];                                            \
    int tid = threadIdx.x;                                                      \
    int row0 = blockIdx.y * 128, col0 = blockIdx.x * 128;                       \
    int wid = tid >> 5, lane = tid & 31, g = lane >> 2, t = lane & 3;           \
    int wm = (wid & 3) * 32, wn = (wid >> 2) * 64;                              \
    (void)lane;                                                                 \
    float c[2][8][4] = {};                                                      \
    float4 pa[4], pb[4];                                                        \
    _Pragma("unroll")                                                           \
    for (int i = 0; i < 4; i++) {                                               \
        int f4 = tid + i * 256;                                                 \
        int rw = f4 >> 3, c4 = (f4 & 7) * 4;                                    \
        pa[i] = *(const float4*)&Aptr[(size_t)(row0 + rw) * Kdim + c4];         \
        int brw = f4 >> 5, bc4 = (f4 & 31) * 4;                                 \
        pb[i] = *(const float4*)&Bptr[(size_t)brw * Ndim + col0 + bc4];         \
    }                                                                           \
    for (int k0c = 0; k0c < Kdim; k0c += 32) {                                  \
        _Pragma("unroll")                                                       \
        for (int i = 0; i < 4; i++) {                                           \
            int f4 = tid + i * 256;                                             \
            int rw = f4 >> 3, c4 = (f4 & 7) * 4;                                \
            *(uint4*)&As[rw][c4] =                                              \
                make_uint4(f2tf(pa[i].x), f2tf(pa[i].y), f2tf(pa[i].z), f2tf(pa[i].w)); \
            int brw = f4 >> 5, bc4 = (f4 & 31) * 4;                             \
            *(uint4*)&Bs[brw][bc4] =                                            \
                make_uint4(f2tf(pb[i].x), f2tf(pb[i].y), f2tf(pb[i].z), f2tf(pb[i].w)); \
        }                                                                       \
        __syncthreads();                                                        \
        if (k0c + 32 < Kdim) {                                                  \
            _Pragma("unroll")                                                   \
            for (int i = 0; i < 4; i++) {                                       \
                int f4 = tid + i * 256;                                         \
                int rw = f4 >> 3, c4 = (f4 & 7) * 4;                            \
                pa[i] = *(const float4*)&Aptr[(size_t)(row0 + rw) * Kdim + k0c + 32 + c4]; \
                int brw = f4 >> 5, bc4 = (f4 & 31) * 4;                         \
                pb[i] = *(const float4*)&Bptr[(size_t)(k0c + 32 + brw) * Ndim + col0 + bc4]; \
            }                                                                   \
        }                                                                       \
        _Pragma("unroll")                                                       \
        for (int k0 = 0; k0 < 32; k0 += 8) {                                    \
            uint32_t a[2][4], b2[8][2];                                         \
            _Pragma("unroll")                                                   \
            for (int mt = 0; mt < 2; mt++) {                                    \
                int r = wm + mt * 16 + g;                                       \
                a[mt][0] = As[r][k0 + t];     a[mt][1] = As[r + 8][k0 + t];     \
                a[mt][2] = As[r][k0 + t + 4]; a[mt][3] = As[r + 8][k0 + t + 4]; \
            }                                                                   \
            _Pragma("unroll")                                                   \
            for (int nt = 0; nt < 8; nt++) {                                    \
                int cn = wn + nt * 8 + g;                                       \
                b2[nt][0] = Bs[k0 + t][cn];                                     \
                b2[nt][1] = Bs[k0 + t + 4][cn];                                 \
            }                                                                   \
            _Pragma("unroll")                                                   \
            for (int mt = 0; mt < 2; mt++)                                      \
                _Pragma("unroll")                                               \
                for (int nt = 0; nt < 8; nt++) mma8(c[mt][nt], a[mt], b2[nt]);  \
        }                                                                       \
        __syncthreads();                                                        \
    }                                                                           \
    __VA_ARGS__

// ---------------- GEMM 1: heads = w @ qkv_w -> Qb/K/V (TF32) -----------------
__global__ __launch_bounds__(256)
void gemm_qkv_kernel(const float* __restrict__ A, const float* __restrict__ B,
                     const float* __restrict__ rbias) {
    NN_TF32_BODY(A, B, 1024, 3072, {
        for (int mt = 0; mt < 2; mt++) {
            for (int rr = 0; rr < 2; rr++) {
                int m = row0 + wm + mt * 16 + g + rr * 8;
                int q = m >> 1;
                int bb = m & 1;
                for (int nt = 0; nt < 8; nt++) {
                    int cc = col0 + wn + nt * 8 + 2 * t;
                    int sec = cc >> 10;
                    int h = (cc & 1023) >> 6;
                    int d = cc & 63;
                    size_t off = ((size_t)(bb * NH + h) * QLEN + q) * DH + d;
                    float vx = c[mt][nt][rr * 2 + 0];
                    float vy = c[mt][nt][rr * 2 + 1];
                    if (sec == 0) {
                        float2 rb = *(const float2*)&rbias[h * 64 + d];
                        float2 v;
                        v.x = vx + rb.x;
                        v.y = vy + rb.y;
                        *(float2*)&g_Qb[off] = v;
                    } else if (sec == 1) {
                        float2 v; v.x = vx; v.y = vy;
                        *(float2*)&g_K[off] = v;
                    } else {
                        float2 v; v.x = vx; v.y = vy;
                        *(float2*)&g_V[off] = v;
                    }
                }
            }
        }
    })
}

// ---------------- GEMM 2: r_head_k = r @ r_net_w -> Rk (TF32) ----------------
__global__ __launch_bounds__(256)
void gemm_rnet_kernel(const float* __restrict__ A, const float* __restrict__ B) {
    NN_TF32_BODY(A, B, 1024, 1024, {
        for (int mt = 0; mt < 2; mt++) {
            for (int rr = 0; rr < 2; rr++) {
                int m = row0 + wm + mt * 16 + g + rr * 8;
                for (int nt = 0; nt < 8; nt++) {
                    int cc = col0 + wn + nt * 8 + 2 * t;
                    int h = cc >> 6;
                    int d = cc & 63;
                    float2 v;
                    v.x = c[mt][nt][rr * 2 + 0];
                    v.y = c[mt][nt][rr * 2 + 1];
                    *(float2*)&g_Rk[((size_t)h * RLEN + m) * DH + d] = v;
                }
            }
        }
    })
}

// ---------------- GEMM 6: output = attn_vec @ o_w (TF32) ---------------------
__global__ __launch_bounds__(256)
void gemm_out_kernel(const float* __restrict__ B, float* __restrict__ out) {
    const float* A = g_AV;
    NN_TF32_BODY(A, B, 1024, 1024, {
        for (int mt = 0; mt < 2; mt++) {
            for (int rr = 0; rr < 2; rr++) {
                int m = row0 + wm + mt * 16 + g + rr * 8;
                for (int nt = 0; nt < 8; nt++) {
                    int cc = col0 + wn + nt * 8 + 2 * t;
                    float2 v;
                    v.x = c[mt][nt][rr * 2 + 0];
                    v.y = c[mt][nt][rr * 2 + 1];
                    *(float2*)&out[(size_t)m * 1024 + cc] = v;
                }
            }
        }
    })
}

// =============================================================================
// Fused score kernel: 64x128 tiles, 256 threads, 2 CTAs/SM, register-prefetched
// band segments (validated r16 band algebra).
// SMEM: BDs[64][196] floats | Qs[65][68] | Ks[128][68] = 102,672 B
// =============================================================================
#define SMEM_STRIDE 68
#define BD_STRIDE2 196
#define BD_WORDS2 (64 * BD_STRIDE2)

__global__ __launch_bounds__(256, 2)
void score_fused_kernel(float* __restrict__ cov) {
    extern __shared__ uint32_t sm[];
    float* BDs = (float*)sm;                                   // 64 x 196 floats
    uint32_t (*Qs)[SMEM_STRIDE] = (uint32_t(*)[SMEM_STRIDE])(sm + BD_WORDS2);          // 65 rows
    uint32_t (*Ks)[SMEM_STRIDE] = (uint32_t(*)[SMEM_STRIDE])(sm + BD_WORDS2 + 65 * SMEM_STRIDE);

    int z = blockIdx.z;
    int b = z >> 4;
    int n = z & (NH - 1);
    const float* Qp  = g_Qb + (size_t)z * QLEN * DH;
    const float* Kp  = g_K  + (size_t)z * KLEN * DH;
    const float* Rkn = g_Rk + (size_t)n * RLEN * DH;
    int row0 = blockIdx.y * 64, col0 = blockIdx.x * 128;
    int tid = threadIdx.x;
    int wid = tid >> 5, lane = tid & 31, g = lane >> 2, t = lane & 3;
    int wm = (wid & 1) * 32, wn = (wid >> 1) * 32;   // AC: 2x4 warp grid, 32x32 tiles
    int d0 = col0 - row0;

    // ---- load Q rows row0..row0+64 (65 rows; last clamped, read only in-range)
#pragma unroll
    for (int i = 0; i < 5; i++) {
        int f4 = tid + i * 256;
        if (f4 < 65 * 16) {
            int rw = f4 >> 4, c4 = (f4 & 15) * 4;
            int qr = row0 + rw; if (qr > 2047) qr = 2047;
            float4 qa = *(const float4*)&Qp[(size_t)qr * DH + c4];
            *(uint4*)&Qs[rw][c4] = make_uint4(f2tf(qa.x), f2tf(qa.y), f2tf(qa.z), f2tf(qa.w));
        }
    }
    // ---- load K tile (128 rows) ----
#pragma unroll
    for (int i = 0; i < 8; i++) {
        int f4 = tid + i * 256;
        int rw = f4 >> 4, c4 = (f4 & 15) * 4;
        float4 kb = *(const float4*)&Kp[(size_t)(col0 + rw) * DH + c4];
        *(uint4*)&Ks[rw][c4] = make_uint4(f2tf(kb.x), f2tf(kb.y), f2tf(kb.z), f2tf(kb.w));
    }
    __syncthreads();

    // ---- prefetch band segment 1 (hides under AC MMA) ----
    float4 pf[4];
    {
        int mainb  = (64 * 1 + 63 <= 127 - d0);
        int rstart = (mainb ? (1920 + d0) : (d0 - 129)) + 64;
#pragma unroll
        for (int i = 0; i < 4; i++) {
            int f4 = tid + i * 256;
            int rw = f4 >> 4, c4 = (f4 & 15) * 4;
            int rr_ = rstart + rw; if (rr_ < 0) rr_ = 0; if (rr_ > 2047) rr_ = 2047;
            pf[i] = *(const float4*)&Rkn[(size_t)rr_ * DH + c4];
        }
    }

    // ---- AC MMA ----
    float c[2][4][4] = {};
#pragma unroll
    for (int k0 = 0; k0 < 64; k0 += 8) {
        uint32_t a[2][4], b2[4][2];
#pragma unroll
        for (int mt = 0; mt < 2; mt++) {
            int r = wm + mt * 16 + g;
            a[mt][0] = Qs[r][k0 + t];     a[mt][1] = Qs[r + 8][k0 + t];
            a[mt][2] = Qs[r][k0 + t + 4]; a[mt][3] = Qs[r + 8][k0 + t + 4];
        }
#pragma unroll
        for (int nt = 0; nt < 4; nt++) {
            int r = wn + nt * 8 + g;
            b2[nt][0] = Ks[r][k0 + t];
            b2[nt][1] = Ks[r][k0 + t + 4];
        }
#pragma unroll
        for (int mt = 0; mt < 2; mt++)
#pragma unroll
            for (int nt = 0; nt < 4; nt++) mma8(c[mt][nt], a[mt], b2[nt]);
    }
    __syncthreads();   // AC done; Ks reusable

    // ---- band segments s = 1..3 (jj in [64s, 64s+64)); pf holds segment s ----
    int bwn = (wid >> 1) * 16;           // band: 2x4 warp grid over 64x64, 32x16 tiles
#pragma unroll 1
    for (int s = 1; s <= 3; s++) {
        int mainb = (64 * s + 63 <= 127 - d0);
        int qoff  = mainb ? 0 : 1;
        // store prefetched segment into Ks[0..64)
#pragma unroll
        for (int i = 0; i < 4; i++) {
            int f4 = tid + i * 256;
            int rw = f4 >> 4, c4 = (f4 & 15) * 4;
            *(uint4*)&Ks[rw][c4] = make_uint4(f2tf(pf[i].x), f2tf(pf[i].y),
                                              f2tf(pf[i].z), f2tf(pf[i].w));
        }
        __syncthreads();
        // prefetch next segment (hides under this segment's MMA)
        if (s < 3) {
            int mainb2  = (64 * (s + 1) + 63 <= 127 - d0);
            int rstart2 = (mainb2 ? (1920 + d0) : (d0 - 129)) + 64 * (s + 1);
#pragma unroll
            for (int i = 0; i < 4; i++) {
                int f4 = tid + i * 256;
                int rw = f4 >> 4, c4 = (f4 & 15) * 4;
                int rr_ = rstart2 + rw; if (rr_ < 0) rr_ = 0; if (rr_ > 2047) rr_ = 2047;
                pf[i] = *(const float4*)&Rkn[(size_t)rr_ * DH + c4];
            }
        }
        float c2[2][2][4] = {};
#pragma unroll
        for (int k0 = 0; k0 < 64; k0 += 8) {
            uint32_t a[2][4], b2[2][2];
#pragma unroll
            for (int mt = 0; mt < 2; mt++) {
                int r = wm + mt * 16 + qoff + g;
                a[mt][0] = Qs[r][k0 + t];     a[mt][1] = Qs[r + 8][k0 + t];
                a[mt][2] = Qs[r][k0 + t + 4]; a[mt][3] = Qs[r + 8][k0 + t + 4];
            }
#pragma unroll
            for (int nt = 0; nt < 2; nt++) {
                int r = bwn + nt * 8 + g;
                b2[nt][0] = Ks[r][k0 + t];
                b2[nt][1] = Ks[r][k0 + t + 4];
            }
#pragma unroll
            for (int mt = 0; mt < 2; mt++)
#pragma unroll
                for (int nt = 0; nt < 2; nt++) mma8(c2[mt][nt], a[mt], b2[nt]);
        }
        // stage into BDs at jjo = 64*(s-1) + local col
#pragma unroll
        for (int mt = 0; mt < 2; mt++)
#pragma unroll
            for (int nt = 0; nt < 2; nt++)
#pragma unroll
                for (int rr = 0; rr < 2; rr++) {
                    int r = wm + mt * 16 + g + rr * 8;
                    int ccol = 64 * (s - 1) + bwn + nt * 8 + 2 * t;
                    float2 v;
                    v.x = c2[mt][nt][rr * 2 + 0];
                    v.y = c2[mt][nt][rr * 2 + 1];
                    *(float2*)&BDs[r * BD_STRIDE2 + ccol] = v;
                }
        __syncthreads();
    }

    // ---- epilogue: s = (AC + BDs[qi][63+kloc-qi]) * scale + negmask ----
    const float* neg = g_negmask + (size_t)b * KLEN;
    float* Cz = cov + (size_t)z * QLEN * KLEN;
#pragma unroll
    for (int mt = 0; mt < 2; mt++) {
        int qi0 = wm + mt * 16 + g;
#pragma unroll
        for (int nt = 0; nt < 4; nt++) {
            int kloc = wn + nt * 8 + 2 * t;
            int kb = col0 + kloc;
            float2 ng = *(const float2*)&neg[kb];
#pragma unroll
            for (int rr = 0; rr < 2; rr++) {
                int qi = qi0 + rr * 8;
                int q = row0 + qi;
                int jjo = 63 + kloc - qi;
                float bdx = (kb     == q + 1) ? 0.0f : BDs[qi * BD_STRIDE2 + jjo];
                float bdy = (kb + 1 == q + 1) ? 0.0f : BDs[qi * BD_STRIDE2 + jjo + 1];
                float2 s;
                s.x = (c[mt][nt][rr * 2 + 0] + bdx) * SCALE_L2E + ng.x;
                s.y = (c[mt][nt][rr * 2 + 1] + bdy) * SCALE_L2E + ng.y;
                *(float2*)&Cz[(size_t)q * KLEN + kb] = s;
            }
        }
    }
}

// ---------------- softmax over k (validated; base-2 domain) ------------------
__global__ __launch_bounds__(256)
void softmax_kernel(float* __restrict__ cov) {
    size_t row = blockIdx.x;
    float* p = cov + row * KLEN;
    int t = threadIdx.x;
    float4 v0 = ((const float4*)p)[t];
    float4 v1 = ((const float4*)p)[t + 256];
    float m = fmaxf(fmaxf(fmaxf(v0.x, v0.y), fmaxf(v0.z, v0.w)),
                    fmaxf(fmaxf(v1.x, v1.y), fmaxf(v1.z, v1.w)));
    __shared__ float sred[8];
#pragma unroll
    for (int o = 16; o; o >>= 1) m = fmaxf(m, __shfl_xor_sync(0xffffffffu, m, o));
    if ((t & 31) == 0) sred[t >> 5] = m;
    __syncthreads();
    if (t < 8) {
        float x = sred[t];
#pragma unroll
        for (int o = 4; o; o >>= 1) x = fmaxf(x, __shfl_xor_sync(0xffu, x, o));
        if (t == 0) sred[0] = x;
    }
    __syncthreads();
    m = sred[0];
    if (m == -INFINITY) {   // fully-masked row -> 0 per reference
        float4 zz = make_float4(0.f, 0.f, 0.f, 0.f);
        ((float4*)p)[t] = zz;
        ((float4*)p)[t + 256] = zz;
        return;
    }
    float e0x = fexp2(v0.x - m), e0y = fexp2(v0.y - m);
    float e0z = fexp2(v0.z - m), e0w = fexp2(v0.w - m);
    float e1x = fexp2(v1.x - m), e1y = fexp2(v1.y - m);
    float e1z = fexp2(v1.z - m), e1w = fexp2(v1.w - m);
    float s = (e0x + e0y) + (e0z + e0w) + (e1x + e1y) + (e1z + e1w);
    __shared__ float ssum[8];
#pragma unroll
    for (int o = 16; o; o >>= 1) s += __shfl_xor_sync(0xffffffffu, s, o);
    if ((t & 31) == 0) ssum[t >> 5] = s;
    __syncthreads();
    if (t < 8) {
        float x = ssum[t];
#pragma unroll
        for (int o = 4; o; o >>= 1) x += __shfl_xor_sync(0xffu, x, o);
        if (t == 0) ssum[0] = x;
    }
    __syncthreads();
    float inv = 1.0f / ssum[0];
    ((float4*)p)[t]       = make_float4(e0x * inv, e0y * inv, e0z * inv, e0w * inv);
    ((float4*)p)[t + 256] = make_float4(e1x * inv, e1y * inv, e1z * inv, e1w * inv);
}

// ---------------- PV: attn_vec = P @ V (TF32 MMA, 64-row tiles; validated r15)
__global__ __launch_bounds__(256)
void pv_mma_kernel(const float* __restrict__ cov) {
    extern __shared__ uint32_t sm[];
    uint32_t (*Ps)[SMEM_STRIDE] = (uint32_t(*)[SMEM_STRIDE])sm;
    uint32_t (*Vs)[SMEM_STRIDE] = (uint32_t(*)[SMEM_STRIDE])(sm + 64 * SMEM_STRIDE);
    int z = blockIdx.y;
    int b = z >> 4, n = z & (NH - 1);
    const float* P = cov + (size_t)z * QLEN * KLEN;
    const float* Vm = g_V + (size_t)z * KLEN * DH;
    int row0 = blockIdx.x * 64;
    int tid = threadIdx.x;
    int wid = tid >> 5, lane = tid & 31, g = lane >> 2, t = lane & 3;
    int wm = (wid & 1) * 32, wn = (wid >> 1) * 16;
    float c[2][2][4] = {};
    for (int kc = 0; kc < KLEN; kc += 64) {
#pragma unroll
        for (int i = 0; i < 4; i++) {
            int f4 = tid + i * 256;
            int rw = f4 >> 4, c4 = (f4 & 15) * 4;
            float4 v = *(const float4*)&P[(size_t)(row0 + rw) * KLEN + kc + c4];
            *(uint4*)&Ps[rw][c4] = make_uint4(f2tf(v.x), f2tf(v.y), f2tf(v.z), f2tf(v.w));
        }
#pragma unroll
        for (int i = 0; i < 4; i++) {
            int f4 = tid + i * 256;
            int rw = f4 >> 4, c4 = (f4 & 15) * 4;
            float4 v = *(const float4*)&Vm[(size_t)(kc + rw) * DH + c4];
            *(uint4*)&Vs[rw][c4] = make_uint4(f2tf(v.x), f2tf(v.y), f2tf(v.z), f2tf(v.w));
        }
        __syncthreads();
#pragma unroll
        for (int k0 = 0; k0 < 64; k0 += 8) {
            uint32_t a[2][4], b2[2][2];
#pragma unroll
            for (int mt = 0; mt < 2; mt++) {
                int r = wm + mt * 16 + g;
                a[mt][0] = Ps[r][k0 + t];     a[mt][1] = Ps[r + 8][k0 + t];
                a[mt][2] = Ps[r][k0 + t + 4]; a[mt][3] = Ps[r + 8][k0 + t + 4];
            }
#pragma unroll
            for (int nt = 0; nt < 2; nt++) {
                int cn = wn + nt * 8 + g;
                b2[nt][0] = Vs[k0 + t][cn];
                b2[nt][1] = Vs[k0 + t + 4][cn];
            }
#pragma unroll
            for (int mt = 0; mt < 2; mt++)
#pragma unroll
                for (int nt = 0; nt < 2; nt++) mma8(c[mt][nt], a[mt], b2[nt]);
        }
        __syncthreads();
    }
#pragma unroll
    for (int mt = 0; mt < 2; mt++) {
        int q0 = row0 + wm + mt * 16 + g;
#pragma unroll
        for (int nt = 0; nt < 2; nt++) {
            int d = wn + nt * 8 + 2 * t;
#pragma unroll
            for (int rr = 0; rr < 2; rr++) {
                int q = q0 + rr * 8;
                float2 v;
                v.x = c[mt][nt][rr * 2 + 0];
                v.y = c[mt][nt][rr * 2 + 1];
                *(float2*)&g_AV[((size_t)q * BSZ + b) * DM + n * DH + d] = v;
            }
        }
    }
}

// ---------------- launch ------------------------------------------------------
extern "C" void kernel_launch(void* const* d_in, const int* in_sizes, int n_in,
                              void* d_out, int out_size) {
    const float* w       = (const float*)d_in[0];
    const float* r       = (const float*)d_in[1];
    const void*  mask    = d_in[2];
    const float* qkv_w   = (const float*)d_in[3];
    const float* r_net_w = (const float*)d_in[4];
    const float* o_w     = (const float*)d_in[5];
    const float* r_r_bias = (const float*)d_in[7];  // reference bug: r_r_bias for both

    float* out = (float*)d_out;
    float* cov = out + (size_t)QLEN * BSZ * DM;

    const int SMEM_FUSED = (BD_WORDS2 + (65 + 128) * SMEM_STRIDE) * 4;  // 102672
    const int SMEM_PV    = (64 + 64) * SMEM_STRIDE * 4;                 // 34816
    static int attr_done = 0;
    if (!attr_done) {
        cudaFuncSetAttribute(score_fused_kernel, cudaFuncAttributeMaxDynamicSharedMemorySize, SMEM_FUSED);
        cudaFuncSetAttribute(pv_mma_kernel,      cudaFuncAttributeMaxDynamicSharedMemorySize, SMEM_PV);
        attr_done = 1;
    }

    mask_expand_kernel<<<1, 256>>>((const unsigned char*)mask);
    gemm_qkv_kernel<<<dim3(24, 32), 256>>>(w, qkv_w, r_r_bias);
    gemm_rnet_kernel<<<dim3(8, 16), 256>>>(r, r_net_w);
    score_fused_kernel<<<dim3(16, 32, BSZ * NH), 256, SMEM_FUSED>>>(cov);
    softmax_kernel<<<BSZ * NH * QLEN, 256>>>(cov);
    pv_mma_kernel<<<dim3(32, BSZ * NH), 256, SMEM_PV>>>(cov);
    gemm_out_kernel<<<dim3(8, 32), 256>>>(o_w, out);
}